// round 15
// baseline (speedup 1.0000x reference)
#include <cuda_runtime.h>
#include <cuda_fp16.h>
#include <math.h>
#include <stdint.h>

#define T_LEN 2048
#define H_HEADS 16
#define KHN 2
#define GQ 8
#define DDIM 128
#define NCMP 127
#define TQ 16
#define SCALE_F 0.08838834765f
#define EXP_SHIFT 10.3972077f   /* ln(2^15) */
#define NEG_INF (-INFINITY)

// ---------------- scratch ----------------
__device__ unsigned g_kmax[KHN];

__device__ __align__(16) __half g_qh16[T_LEN * H_HEADS * DDIM];
__device__ __align__(16) __half g_ql16[T_LEN * H_HEADS * DDIM];
__device__ __align__(16) __half g_kh16[KHN * T_LEN * DDIM];
__device__ __align__(16) __half g_vh16[KHN * T_LEN * DDIM];
__device__ __align__(16) __half g_ckhi[KHN][128][DDIM];
__device__ __align__(16) __half g_cklo[KHN][128][DDIM];
__device__ __align__(16) __half g_cvhi[KHN][128][DDIM];

// ---------------- helpers ----------------
__device__ __forceinline__ uint32_t smem_u32(const void* p) {
    uint32_t a;
    asm("{ .reg .u64 t; cvta.to.shared.u64 t, %1; cvt.u32.u64 %0, t; }" : "=r"(a) : "l"(p));
    return a;
}
__device__ __forceinline__ void mma16816h(float* d, const uint32_t* a, uint32_t b0, uint32_t b1) {
    asm volatile("mma.sync.aligned.m16n8k16.row.col.f32.f16.f16.f32 "
        "{%0,%1,%2,%3},{%4,%5,%6,%7},{%8,%9},{%0,%1,%2,%3};"
        : "+f"(d[0]), "+f"(d[1]), "+f"(d[2]), "+f"(d[3])
        : "r"(a[0]), "r"(a[1]), "r"(a[2]), "r"(a[3]), "r"(b0), "r"(b1));
}
__device__ __forceinline__ void ldsm4(uint32_t* r, uint32_t addr) {
    asm volatile("ldmatrix.sync.aligned.m8n8.x4.shared.b16 {%0,%1,%2,%3}, [%4];"
        : "=r"(r[0]), "=r"(r[1]), "=r"(r[2]), "=r"(r[3]) : "r"(addr));
}
__device__ __forceinline__ void ldsm4t(uint32_t* r, uint32_t addr) {
    asm volatile("ldmatrix.sync.aligned.m8n8.x4.trans.shared.b16 {%0,%1,%2,%3}, [%4];"
        : "=r"(r[0]), "=r"(r[1]), "=r"(r[2]), "=r"(r[3]) : "r"(addr));
}
__device__ __forceinline__ uint32_t packh2(float a, float b) {
    __half2 h = __floats2half2_rn(a, b);
    return *reinterpret_cast<uint32_t*>(&h);
}
#define CP_ASYNC16(dst, src) \
    asm volatile("cp.async.cg.shared.global [%0], [%1], 16;" :: "r"(dst), "l"(src) : "memory")
#define CP_COMMIT() asm volatile("cp.async.commit_group;" ::: "memory")
#define CP_WAIT0()  asm volatile("cp.async.wait_group 0;" ::: "memory")

// ---------------- K0: pre-split ----------------
__global__ void k0_split(const float* __restrict__ q, const float* __restrict__ k,
                         const float* __restrict__ v) {
    int stride = gridDim.x * blockDim.x;
    int idx = blockIdx.x * blockDim.x + threadIdx.x;
    const int n_kv = T_LEN * KHN * DDIM;
    for (int i = idx; i < n_kv; i += stride) {
        int d = i & (DDIM - 1);
        int tk = i >> 7;
        int kh = tk & 1, t = tk >> 1;
        int o = (kh * T_LEN + t) * DDIM + d;
        g_kh16[o] = __float2half_rn(k[i]);
        g_vh16[o] = __float2half_rn(v[i]);
    }
    const int n_q = T_LEN * H_HEADS * DDIM;
    for (int i = idx; i < n_q; i += stride) {
        float x = q[i];
        __half hh = __float2half_rn(x);
        g_qh16[i] = hh;
        g_ql16[i] = __float2half_rn(x - __half2float(hh));
    }
}

// ---------------- K1: compressed K/V ----------------
__global__ void k1_compress(const float* __restrict__ k, const float* __restrict__ v) {
    int j = blockIdx.x, kh = blockIdx.y, d = threadIdx.x;
    int s = j * 16;
    float sk = 0.f, sv = 0.f;
#pragma unroll 8
    for (int i = 0; i < 32; i++) {
        sk += k[((size_t)(s + i) * KHN + kh) * DDIM + d];
        sv += v[((size_t)(s + i) * KHN + kh) * DDIM + d];
    }
    float ck = sk * (1.f / 32.f), cv = sv * (1.f / 32.f);
    __half h = __float2half_rn(ck);
    g_ckhi[kh][j][d] = h;
    g_cklo[kh][j][d] = __float2half_rn(ck - __half2float(h));
    g_cvhi[kh][j][d] = __float2half_rn(cv);
}

// ---------------- K1b: max ||k_row|| ----------------
__global__ void k1b_knorm(const float* __restrict__ k) {
    int t = blockIdx.x, kh = blockIdx.y, lane = threadIdx.x;
    const float4* kr = reinterpret_cast<const float4*>(k) + ((size_t)t * KHN + kh) * 32;
    float4 a = kr[lane];
    float s = a.x * a.x + a.y * a.y + a.z * a.z + a.w * a.w;
    for (int o = 16; o; o >>= 1) s += __shfl_xor_sync(0xffffffffu, s, o);
    if (lane == 0) atomicMax(&g_kmax[kh], __float_as_uint(sqrtf(s)));
}

// ---------------- K23: fused ----------------
#define SQH   0
#define SQL   32768
#define SCKH  65536
#define SCKL  98304
#define SPS   131072
#define SOC   98304
#define SBUF  32768
#define BUFSZ 32768
#define VHIO  16384
#define SMTOT 163840

__global__ __launch_bounds__(256, 1) void k23_fused(
    const float* __restrict__ q, const float* __restrict__ w,
    float* __restrict__ out)
{
    extern __shared__ char smem[];
    uint32_t sb = smem_u32(smem);
    float* psum_sh = reinterpret_cast<float*>(smem + SPS);
    float* oc_sh = reinterpret_cast<float*>(smem + SOC);
    int tid = threadIdx.x;
    int wp = tid >> 5, lane = tid & 31;
    int ridx = (int)gridDim.x - 1 - (int)blockIdx.x;
    int tile = ridx >> 1;
    int kh = ridx & 1;
    int t0 = tile * TQ;
    int grp = lane >> 3;
    int jcl = (lane & 3) * 2;

    __shared__ int s_list[36];
    __shared__ int s_n;
    __shared__ unsigned s_union;

    int t_a = t0 + 2 * wp;
    int t_b = t_a + 1;
    int g = lane >> 2;
    int h = kh * GQ + g;

    if (tid == 0) s_union = 0u;

    // ---- stage QH/QL + CKH/CKL ----
    for (int i = tid; i < 128 * 16; i += 256) {
        int row = i >> 4, c16 = i & 15;
        uint32_t off = (uint32_t)row * 256u + (uint32_t)((c16 ^ (row & 7)) << 4);
        int qrow = (t0 + (row >> 3)) * H_HEADS + kh * GQ + (row & 7);
        CP_ASYNC16(sb + SQH + off, g_qh16 + (size_t)qrow * DDIM + c16 * 8);
        CP_ASYNC16(sb + SQL + off, g_ql16 + (size_t)qrow * DDIM + c16 * 8);
        CP_ASYNC16(sb + SCKH + off, &g_ckhi[kh][row][c16 * 8]);
        CP_ASYNC16(sb + SCKL + off, &g_cklo[kh][row][c16 * 8]);
    }
    CP_COMMIT();

    float kmaxv = __uint_as_float(g_kmax[kh]);
    float Ua, Ub;
    {
        const float4* q4 = reinterpret_cast<const float4*>(q);
        float s2 = 0.f;
        const float4* qr = q4 + ((size_t)(t_a * H_HEADS + h)) * 32;
#pragma unroll 8
        for (int d4 = 0; d4 < 32; d4++) { float4 a = qr[d4]; s2 += a.x*a.x + a.y*a.y + a.z*a.z + a.w*a.w; }
        Ua = SCALE_F * sqrtf(s2) * kmaxv - EXP_SHIFT;
        s2 = 0.f;
        qr = q4 + ((size_t)(t_b * H_HEADS + h)) * 32;
#pragma unroll 8
        for (int d4 = 0; d4 < 32; d4++) { float4 a = qr[d4]; s2 += a.x*a.x + a.y*a.y + a.z*a.z + a.w*a.w; }
        Ub = SCALE_F * sqrtf(s2) * kmaxv - EXP_SHIFT;
    }

    CP_WAIT0();
    __syncthreads();

    int nva = (t_a >= 31) ? ((t_a - 31) / 16 + 1) : 0;
    int nvb = (t_b >= 31) ? ((t_b - 31) / 16 + 1) : 0;

    // ---- Q-hi fragments (both phases) ----
    uint32_t ah[8][4];
    {
        int row = 16 * wp + (grp & 1) * 8 + (lane & 7);
        uint32_t rb = (uint32_t)row * 256u, rx = (uint32_t)(row & 7);
#pragma unroll
        for (int kt = 0; kt < 8; kt++) {
            uint32_t cq = (uint32_t)(kt * 2 + (grp >> 1));
            ldsm4(ah[kt], sb + SQH + rb + ((cq ^ rx) << 4));
        }
    }

    unsigned selm_a, selm_b;
    const __half* khbase = g_kh16 + (size_t)kh * T_LEN * DDIM;
    const __half* vhbase = g_vh16 + (size_t)kh * T_LEN * DDIM;

    // ================= PHASE 1 =================
    {
        float s[16][4];
#pragma unroll
        for (int i = 0; i < 16; i++)
#pragma unroll
            for (int c = 0; c < 4; c++) s[i][c] = 0.f;

#pragma unroll
        for (int np = 0; np < 8; np++) {
            if (np * 16 < nvb) {
                int keyq = np * 16 + (grp >> 1) * 8 + (lane & 7);
                uint32_t kb = (uint32_t)keyq * 256u, rxk = (uint32_t)(keyq & 7);
                int rowq = 16 * wp + (grp & 1) * 8 + (lane & 7);
                uint32_t rq = (uint32_t)rowq * 256u, rxq = (uint32_t)(rowq & 7);
#pragma unroll
                for (int kt = 0; kt < 8; kt++) {
                    uint32_t ck = (uint32_t)(kt * 2 + (grp & 1));
                    uint32_t bo = kb + ((ck ^ rxk) << 4);
                    uint32_t cq = (uint32_t)(kt * 2 + (grp >> 1));
                    uint32_t bh[4], bl[4], al[4];
                    ldsm4(bh, sb + SCKH + bo);
                    ldsm4(bl, sb + SCKL + bo);
                    ldsm4(al, sb + SQL + rq + ((cq ^ rxq) << 4));
                    mma16816h(s[2*np],   ah[kt], bh[0], bh[1]);
                    mma16816h(s[2*np+1], ah[kt], bh[2], bh[3]);
                    mma16816h(s[2*np],   ah[kt], bl[0], bl[1]);
                    mma16816h(s[2*np+1], ah[kt], bl[2], bl[3]);
                    mma16816h(s[2*np],   al,     bh[0], bh[1]);
                    mma16816h(s[2*np+1], al,     bh[2], bh[3]);
                }
            }
        }
        __syncthreads();

        for (int i = tid; i < 128 * 16; i += 256) {
            int row = i >> 4, c16 = i & 15;
            uint32_t off = (uint32_t)row * 256u + (uint32_t)((c16 ^ (row & 7)) << 4);
            CP_ASYNC16(sb + SCKH + off, &g_cvhi[kh][row][c16 * 8]);
        }
        for (int i = tid; i < 1024; i += 256) {
            int row = i >> 4, c16 = i & 15;
            size_t src = (size_t)row * DDIM + c16 * 8;
            uint32_t dst = sb + SBUF + ((uint32_t)row * 256u + (uint32_t)((c16 ^ (row & 7)) << 4));
            CP_ASYNC16(dst, khbase + src);
            CP_ASYNC16(dst + VHIO, vhbase + src);
        }
        CP_COMMIT();

        float ma = NEG_INF, mb = NEG_INF;
#pragma unroll
        for (int nt = 0; nt < 16; nt++) {
            if ((nt >> 1) * 16 < nvb) {
                int j0 = nt * 8 + jcl;
                if (j0 < nva)     ma = fmaxf(ma, s[nt][0] * SCALE_F);
                if (j0 + 1 < nva) ma = fmaxf(ma, s[nt][1] * SCALE_F);
                if (j0 < nvb)     mb = fmaxf(mb, s[nt][2] * SCALE_F);
                if (j0 + 1 < nvb) mb = fmaxf(mb, s[nt][3] * SCALE_F);
            }
        }
#pragma unroll
        for (int o = 1; o <= 2; o <<= 1) {
            ma = fmaxf(ma, __shfl_xor_sync(0xffffffffu, ma, o));
            mb = fmaxf(mb, __shfl_xor_sync(0xffffffffu, mb, o));
        }
        float la = 0.f, lb = 0.f;
#pragma unroll
        for (int nt = 0; nt < 16; nt++) {
            if ((nt >> 1) * 16 < nvb) {
                int j0 = nt * 8 + jcl;
                float e0 = (j0 < nva)     ? __expf(s[nt][0] * SCALE_F - ma) : 0.f;
                float e1 = (j0 + 1 < nva) ? __expf(s[nt][1] * SCALE_F - ma) : 0.f;
                float e2 = (j0 < nvb)     ? __expf(s[nt][2] * SCALE_F - mb) : 0.f;
                float e3 = (j0 + 1 < nvb) ? __expf(s[nt][3] * SCALE_F - mb) : 0.f;
                s[nt][0] = e0; s[nt][1] = e1; s[nt][2] = e2; s[nt][3] = e3;
                la += e0 + e1; lb += e2 + e3;
            }
        }
#pragma unroll
        for (int o = 1; o <= 2; o <<= 1) {
            la += __shfl_xor_sync(0xffffffffu, la, o);
            lb += __shfl_xor_sync(0xffffffffu, lb, o);
        }
        float inva = (nva > 0) ? 1.f / la : 0.f;
        float invb = (nvb > 0) ? 1.f / lb : 0.f;
#pragma unroll
        for (int nt = 0; nt < 16; nt++) {
            if ((nt >> 1) * 16 < nvb) {
                s[nt][0] *= inva; s[nt][1] *= inva;
                s[nt][2] *= invb; s[nt][3] *= invb;
            }
        }

#pragma unroll
        for (int nt = 0; nt < 16; nt++) {
            if ((nt >> 1) * 16 < nvb) {
                float a0 = s[nt][0], a1 = s[nt][1], b0 = s[nt][2], b1 = s[nt][3];
#pragma unroll
                for (int o = 4; o <= 16; o <<= 1) {
                    a0 += __shfl_xor_sync(0xffffffffu, a0, o);
                    a1 += __shfl_xor_sync(0xffffffffu, a1, o);
                    b0 += __shfl_xor_sync(0xffffffffu, b0, o);
                    b1 += __shfl_xor_sync(0xffffffffu, b1, o);
                }
                if (lane < 4) {
                    int j = nt * 8 + lane * 2;
                    psum_sh[(2 * wp) * 128 + j] = a0;
                    psum_sh[(2 * wp) * 128 + j + 1] = a1;
                    psum_sh[(2 * wp + 1) * 128 + j] = b0;
                    psum_sh[(2 * wp + 1) * 128 + j + 1] = b1;
                }
            }
        }
        __syncthreads();

        unsigned selres[2];
#pragma unroll
        for (int rep = 0; rep < 2; rep++) {
            int t = t0 + 2 * wp + rep;
            int qi = 2 * wp + rep;
            int nv = (t >= 31) ? ((t - 31) / 16 + 1) : 0;
            int b = lane;
            int tb = t >> 6;
            bool forced = (b < 1) || ((b <= tb) && (b >= tb - 1));
            bool valid = (b * 64 <= t);
            float sc;
            if (!valid) sc = -1e30f;
            else if (forced) sc = 1e30f;
            else {
                int jlo = 4 * b - 1; if (jlo < 0) jlo = 0;
                int jhi = 4 * b + 3; if (jhi > nv - 1) jhi = nv - 1;
                float ss = 0.f;
                for (int j = jlo; j <= jhi; j++) ss += psum_sh[qi * 128 + j];
                sc = ss;
            }
            unsigned u = __float_as_uint(sc);
            u = ((int)u < 0) ? ~u : (u | 0x80000000u);
            unsigned sel = 0u;
            for (int it = 0; it < 16; it++) {
                unsigned cur = ((sel >> b) & 1u) ? 0u : u;
                unsigned m = __reduce_max_sync(0xffffffffu, cur);
                unsigned ball = __ballot_sync(0xffffffffu, cur == m);
                sel |= (1u << (__ffs(ball) - 1));
            }
            selres[rep] = sel;
        }
        selm_a = selres[0];
        selm_b = selres[1];
        if (lane == 0) atomicOr(&s_union, selm_a | selm_b);

        uint32_t ph[8][4];
#pragma unroll
        for (int kp = 0; kp < 8; kp++) {
            if (kp * 16 < nvb) {
                ph[kp][0] = packh2(s[2*kp][0],   s[2*kp][1]);
                ph[kp][1] = packh2(s[2*kp][2],   s[2*kp][3]);
                ph[kp][2] = packh2(s[2*kp+1][0], s[2*kp+1][1]);
                ph[kp][3] = packh2(s[2*kp+1][2], s[2*kp+1][3]);
            }
        }

        CP_WAIT0();
        __syncthreads();

        float Oc[16][4];
#pragma unroll
        for (int i = 0; i < 16; i++)
#pragma unroll
            for (int c = 0; c < 4; c++) Oc[i][c] = 0.f;
#pragma unroll
        for (int kp = 0; kp < 8; kp++) {
            if (kp * 16 < nvb) {
                int keyv = kp * 16 + (grp & 1) * 8 + (lane & 7);
                uint32_t kb = (uint32_t)keyv * 256u, rxv = (uint32_t)(keyv & 7);
#pragma unroll
                for (int dp = 0; dp < 8; dp++) {
                    uint32_t c16 = (uint32_t)(dp * 2 + (grp >> 1));
                    uint32_t off = kb + ((c16 ^ rxv) << 4);
                    uint32_t vh[4];
                    ldsm4t(vh, sb + SCKH + off);
                    mma16816h(Oc[2*dp],   ph[kp], vh[0], vh[1]);
                    mma16816h(Oc[2*dp+1], ph[kp], vh[2], vh[3]);
                }
            }
        }
        __syncthreads();

#pragma unroll
        for (int nt = 0; nt < 16; nt++)
#pragma unroll
            for (int c = 0; c < 4; c++)
                oc_sh[(nt * 4 + c) * 256 + tid] = Oc[nt][c];
    }

    // ================= PHASE 2 =================
    __syncthreads();
    unsigned selu = s_union;
    int t_blk = t0 >> 6;

    if (tid == 0) {
        int n = 0;
        for (int b = 0; b <= t_blk; b++) {
            bool need = ((selu >> b) & 1u) || (b * 64 + 63 >= t0 - 511);
            if (need) s_list[n++] = b;
        }
        s_n = n;
    }
    __syncthreads();
    int nch = s_n;

    float Os[16][4], Ow[16][4];
#pragma unroll
    for (int i = 0; i < 16; i++)
#pragma unroll
        for (int c = 0; c < 4; c++) { Os[i][c] = 0.f; Ow[i][c] = 0.f; }
    float sum_sa = 0.f, sum_sb = 0.f, sum_wa = 0.f, sum_wb = 0.f;
    unsigned selw = selm_a | selm_b;
    int wlo = t_a - 511;   // union window lower bound for this warp's rows

    for (int ci = 0; ci < nch; ci++) {
        int b = s_list[ci];
        uint32_t KB = sb + SBUF + (uint32_t)(ci & 1) * BUFSZ;

        if (ci > 0) {
            CP_WAIT0();
            __syncthreads();
        }
        if (ci + 1 < nch) {
            int bn = s_list[ci + 1];
            uint32_t NB = sb + SBUF + (uint32_t)((ci + 1) & 1) * BUFSZ;
            for (int i = tid; i < 1024; i += 256) {
                int row = i >> 4, c16 = i & 15;
                size_t src = (size_t)(bn * 64 + row) * DDIM + c16 * 8;
                uint32_t dst = NB + ((uint32_t)row * 256u + (uint32_t)((c16 ^ (row & 7)) << 4));
                CP_ASYNC16(dst, khbase + src);
                CP_ASYNC16(dst + VHIO, vhbase + src);
            }
            CP_COMMIT();
        }

        bool sel_w = (selw >> b) & 1u;
        bool win_w = (b * 64 + 63 >= wlo);
        if (!sel_w && !win_w) continue;
        bool sa = (selm_a >> b) & 1u, sb2 = (selm_b >> b) & 1u;
        bool limit_hi = (b == t_blk);                 // causal edge chunk
        bool limit_lo = win_w && !sel_w && (b * 64 < wlo);  // win-only entry chunk
        bool needs_wm = win_w && (b * 64 < t_b - 511);
        bool fast = !limit_hi && !needs_wm;

#pragma unroll
        for (int np = 0; np < 4; np++) {
            int base = b * 64 + np * 16;
            // exact 16-key slab skipping: masked-to-zero slabs produce zero MMAs
            if (limit_hi && base > t_b) continue;
            if (limit_lo && base + 15 < wlo) continue;

            float s0[4] = {0.f, 0.f, 0.f, 0.f}, s1[4] = {0.f, 0.f, 0.f, 0.f};
            {
                int keyq = np * 16 + (grp >> 1) * 8 + (lane & 7);
                uint32_t kb = (uint32_t)keyq * 256u, rxk = (uint32_t)(keyq & 7);
#pragma unroll
                for (int kt = 0; kt < 8; kt++) {
                    uint32_t ck = (uint32_t)(kt * 2 + (grp & 1));
                    uint32_t bh[4];
                    ldsm4(bh, KB + kb + ((ck ^ rxk) << 4));
                    mma16816h(s0, ah[kt], bh[0], bh[1]);
                    mma16816h(s1, ah[kt], bh[2], bh[3]);
                }
            }
            float ea0 = __expf(s0[0] * SCALE_F - Ua);
            float ea1 = __expf(s0[1] * SCALE_F - Ua);
            float eb0 = __expf(s0[2] * SCALE_F - Ub);
            float eb1 = __expf(s0[3] * SCALE_F - Ub);
            float fa0 = __expf(s1[0] * SCALE_F - Ua);
            float fa1 = __expf(s1[1] * SCALE_F - Ua);
            float fb0 = __expf(s1[2] * SCALE_F - Ub);
            float fb1 = __expf(s1[3] * SCALE_F - Ub);

            uint32_t ps[4], pw[4];
            if (fast) {
                if (sel_w) {
                    float v0 = sa ? ea0 : 0.f, v1 = sa ? ea1 : 0.f;
                    float v2 = sb2 ? eb0 : 0.f, v3 = sb2 ? eb1 : 0.f;
                    float v4 = sa ? fa0 : 0.f, v5 = sa ? fa1 : 0.f;
                    float v6 = sb2 ? fb0 : 0.f, v7 = sb2 ? fb1 : 0.f;
                    sum_sa += v0 + v1 + v4 + v5;
                    sum_sb += v2 + v3 + v6 + v7;
                    ps[0] = packh2(v0, v1); ps[1] = packh2(v2, v3);
                    ps[2] = packh2(v4, v5); ps[3] = packh2(v6, v7);
                }
                if (win_w) {
                    sum_wa += ea0 + ea1 + fa0 + fa1;
                    sum_wb += eb0 + eb1 + fb0 + fb1;
                    pw[0] = packh2(ea0, ea1); pw[1] = packh2(eb0, eb1);
                    pw[2] = packh2(fa0, fa1); pw[3] = packh2(fb0, fb1);
                }
            } else {
                int j0 = base + jcl;
                int j1 = j0 + 1, j8 = j0 + 8, j9 = j0 + 9;
                if (sel_w) {
                    float v0 = (sa  && j0 <= t_a) ? ea0 : 0.f;
                    float v1 = (sa  && j1 <= t_a) ? ea1 : 0.f;
                    float v2 = (sb2 && j0 <= t_b) ? eb0 : 0.f;
                    float v3 = (sb2 && j1 <= t_b) ? eb1 : 0.f;
                    float v4 = (sa  && j8 <= t_a) ? fa0 : 0.f;
                    float v5 = (sa  && j9 <= t_a) ? fa1 : 0.f;
                    float v6 = (sb2 && j8 <= t_b) ? fb0 : 0.f;
                    float v7 = (sb2 && j9 <= t_b) ? fb1 : 0.f;
                    sum_sa += v0 + v1 + v4 + v5;
                    sum_sb += v2 + v3 + v6 + v7;
                    ps[0] = packh2(v0, v1); ps[1] = packh2(v2, v3);
                    ps[2] = packh2(v4, v5); ps[3] = packh2(v6, v7);
                }
                if (win_w) {
                    float v0 = (j0 <= t_a && t_a - j0 < 512) ? ea0 : 0.f;
                    float v1 = (j1 <= t_a && t_a - j1 < 512) ? ea1 : 0.f;
                    float v2 = (j0 <= t_b && t_b - j0 < 512) ? eb0 : 0.f;
                    float v3 = (j1 <= t_b && t_b - j1 < 512) ? eb1 : 0.f;
                    float v4 = (j8 <= t_a && t_a - j8 < 512) ? fa0 : 0.f;
                    float v5 = (j9 <= t_a && t_a - j9 < 512) ? fa1 : 0.f;
                    float v6 = (j8 <= t_b && t_b - j8 < 512) ? fb0 : 0.f;
                    float v7 = (j9 <= t_b && t_b - j9 < 512) ? fb1 : 0.f;
                    sum_wa += v0 + v1 + v4 + v5;
                    sum_wb += v2 + v3 + v6 + v7;
                    pw[0] = packh2(v0, v1); pw[1] = packh2(v2, v3);
                    pw[2] = packh2(v4, v5); pw[3] = packh2(v6, v7);
                }
            }

            {
                int keyv = np * 16 + (grp & 1) * 8 + (lane & 7);
                uint32_t kb = (uint32_t)keyv * 256u, rxv = (uint32_t)(keyv & 7);
#pragma unroll
                for (int dp = 0; dp < 8; dp++) {
                    uint32_t c16 = (uint32_t)(dp * 2 + (grp >> 1));
                    uint32_t off = kb + ((c16 ^ rxv) << 4);
                    uint32_t vh[4];
                    ldsm4t(vh, KB + VHIO + off);
                    if (sel_w) {
                        mma16816h(Os[2 * dp],     ps, vh[0], vh[1]);
                        mma16816h(Os[2 * dp + 1], ps, vh[2], vh[3]);
                    }
                    if (win_w) {
                        mma16816h(Ow[2 * dp],     pw, vh[0], vh[1]);
                        mma16816h(Ow[2 * dp + 1], pw, vh[2], vh[3]);
                    }
                }
            }
        }
    }

    // ---- epilogue ----
#pragma unroll
    for (int o = 1; o <= 2; o <<= 1) {
        sum_sa += __shfl_xor_sync(0xffffffffu, sum_sa, o);
        sum_sb += __shfl_xor_sync(0xffffffffu, sum_sb, o);
        sum_wa += __shfl_xor_sync(0xffffffffu, sum_wa, o);
        sum_wb += __shfl_xor_sync(0xffffffffu, sum_wb, o);
    }
    float inv_sa = 1.f / sum_sa, inv_sb = 1.f / sum_sb;
    float inv_wa = 1.f / sum_wa, inv_wb = 1.f / sum_wb;

    const float* wa = w + ((size_t)(t_a * H_HEADS + h)) * 3;
    const float* wb = w + ((size_t)(t_b * H_HEADS + h)) * 3;
    float w0a = wa[0], w1a = wa[1], w2a = wa[2];
    float w0b = wb[0], w1b = wb[1], w2b = wb[2];

#pragma unroll
    for (int nt = 0; nt < 16; nt++) {
        int d0 = nt * 8 + jcl;
        float oca0 = oc_sh[(nt * 4 + 0) * 256 + tid];
        float oca1 = oc_sh[(nt * 4 + 1) * 256 + tid];
        float ocb0 = oc_sh[(nt * 4 + 2) * 256 + tid];
        float ocb1 = oc_sh[(nt * 4 + 3) * 256 + tid];
        float2 oa, ob;
        oa.x = w0a * oca0 + w1a * Os[nt][0] * inv_sa + w2a * Ow[nt][0] * inv_wa;
        oa.y = w0a * oca1 + w1a * Os[nt][1] * inv_sa + w2a * Ow[nt][1] * inv_wa;
        ob.x = w0b * ocb0 + w1b * Os[nt][2] * inv_sb + w2b * Ow[nt][2] * inv_wb;
        ob.y = w0b * ocb1 + w1b * Os[nt][3] * inv_sb + w2b * Ow[nt][3] * inv_wb;
        *reinterpret_cast<float2*>(out + ((size_t)(t_a * H_HEADS + h)) * DDIM + d0) = oa;
        *reinterpret_cast<float2*>(out + ((size_t)(t_b * H_HEADS + h)) * DDIM + d0) = ob;
    }
}

// ---------------- launch ----------------
extern "C" void kernel_launch(void* const* d_in, const int* in_sizes, int n_in,
                              void* d_out, int out_size) {
    const float* q = (const float*)d_in[0];
    const float* k = (const float*)d_in[1];
    const float* v = (const float*)d_in[2];
    const float* w = (const float*)d_in[3];
    float* out = (float*)d_out;

    cudaFuncSetAttribute(k23_fused, cudaFuncAttributeMaxDynamicSharedMemorySize, SMTOT);

    k0_split<<<1024, 256>>>(q, k, v);
    k1_compress<<<dim3(NCMP, KHN), DDIM>>>(k, v);
    k1b_knorm<<<dim3(T_LEN, KHN), 32>>>(k);
    k23_fused<<<dim3(T_LEN / TQ * KHN, 1), 256, SMTOT>>>(q, w, out);
}

// round 16
// speedup vs baseline: 1.0344x; 1.0344x over previous
#include <cuda_runtime.h>
#include <cuda_fp16.h>
#include <math.h>
#include <stdint.h>

#define T_LEN 2048
#define H_HEADS 16
#define KHN 2
#define GQ 8
#define DDIM 128
#define NCMP 127
#define TQ 16
#define SCALE_F 0.08838834765f
#define EXP_SHIFT 10.3972077f   /* ln(2^15) */
#define NEG_INF (-INFINITY)

// ---------------- scratch ----------------
__device__ unsigned g_kmax[KHN];

__device__ __align__(16) __half g_qh16[T_LEN * H_HEADS * DDIM];
__device__ __align__(16) __half g_ql16[T_LEN * H_HEADS * DDIM];
__device__ __align__(16) __half g_kh16[KHN * T_LEN * DDIM];
__device__ __align__(16) __half g_vh16[KHN * T_LEN * DDIM];
__device__ __align__(16) __half g_ckhi[KHN][128][DDIM];
__device__ __align__(16) __half g_cklo[KHN][128][DDIM];
__device__ __align__(16) __half g_cvhi[KHN][128][DDIM];

// ---------------- helpers ----------------
__device__ __forceinline__ uint32_t smem_u32(const void* p) {
    uint32_t a;
    asm("{ .reg .u64 t; cvta.to.shared.u64 t, %1; cvt.u32.u64 %0, t; }" : "=r"(a) : "l"(p));
    return a;
}
__device__ __forceinline__ void mma16816h(float* d, const uint32_t* a, uint32_t b0, uint32_t b1) {
    asm volatile("mma.sync.aligned.m16n8k16.row.col.f32.f16.f16.f32 "
        "{%0,%1,%2,%3},{%4,%5,%6,%7},{%8,%9},{%0,%1,%2,%3};"
        : "+f"(d[0]), "+f"(d[1]), "+f"(d[2]), "+f"(d[3])
        : "r"(a[0]), "r"(a[1]), "r"(a[2]), "r"(a[3]), "r"(b0), "r"(b1));
}
__device__ __forceinline__ void ldsm4(uint32_t* r, uint32_t addr) {
    asm volatile("ldmatrix.sync.aligned.m8n8.x4.shared.b16 {%0,%1,%2,%3}, [%4];"
        : "=r"(r[0]), "=r"(r[1]), "=r"(r[2]), "=r"(r[3]) : "r"(addr));
}
__device__ __forceinline__ void ldsm4t(uint32_t* r, uint32_t addr) {
    asm volatile("ldmatrix.sync.aligned.m8n8.x4.trans.shared.b16 {%0,%1,%2,%3}, [%4];"
        : "=r"(r[0]), "=r"(r[1]), "=r"(r[2]), "=r"(r[3]) : "r"(addr));
}
__device__ __forceinline__ uint32_t packh2(float a, float b) {
    __half2 h = __floats2half2_rn(a, b);
    return *reinterpret_cast<uint32_t*>(&h);
}
#define CP_ASYNC16(dst, src) \
    asm volatile("cp.async.cg.shared.global [%0], [%1], 16;" :: "r"(dst), "l"(src) : "memory")
#define CP_COMMIT() asm volatile("cp.async.commit_group;" ::: "memory")
#define CP_WAIT0()  asm volatile("cp.async.wait_group 0;" ::: "memory")

// ---------------- K0: pre-split ----------------
__global__ void k0_split(const float* __restrict__ q, const float* __restrict__ k,
                         const float* __restrict__ v) {
    int stride = gridDim.x * blockDim.x;
    int idx = blockIdx.x * blockDim.x + threadIdx.x;
    const int n_kv = T_LEN * KHN * DDIM;
    for (int i = idx; i < n_kv; i += stride) {
        int d = i & (DDIM - 1);
        int tk = i >> 7;
        int kh = tk & 1, t = tk >> 1;
        int o = (kh * T_LEN + t) * DDIM + d;
        g_kh16[o] = __float2half_rn(k[i]);
        g_vh16[o] = __float2half_rn(v[i]);
    }
    const int n_q = T_LEN * H_HEADS * DDIM;
    for (int i = idx; i < n_q; i += stride) {
        float x = q[i];
        __half hh = __float2half_rn(x);
        g_qh16[i] = hh;
        g_ql16[i] = __float2half_rn(x - __half2float(hh));
    }
}

// ---------------- K1: compressed K/V ----------------
__global__ void k1_compress(const float* __restrict__ k, const float* __restrict__ v) {
    int j = blockIdx.x, kh = blockIdx.y, d = threadIdx.x;
    int s = j * 16;
    float sk = 0.f, sv = 0.f;
#pragma unroll 8
    for (int i = 0; i < 32; i++) {
        sk += k[((size_t)(s + i) * KHN + kh) * DDIM + d];
        sv += v[((size_t)(s + i) * KHN + kh) * DDIM + d];
    }
    float ck = sk * (1.f / 32.f), cv = sv * (1.f / 32.f);
    __half h = __float2half_rn(ck);
    g_ckhi[kh][j][d] = h;
    g_cklo[kh][j][d] = __float2half_rn(ck - __half2float(h));
    g_cvhi[kh][j][d] = __float2half_rn(cv);
}

// ---------------- K1b: max ||k_row|| ----------------
__global__ void k1b_knorm(const float* __restrict__ k) {
    int t = blockIdx.x, kh = blockIdx.y, lane = threadIdx.x;
    const float4* kr = reinterpret_cast<const float4*>(k) + ((size_t)t * KHN + kh) * 32;
    float4 a = kr[lane];
    float s = a.x * a.x + a.y * a.y + a.z * a.z + a.w * a.w;
    for (int o = 16; o; o >>= 1) s += __shfl_xor_sync(0xffffffffu, s, o);
    if (lane == 0) atomicMax(&g_kmax[kh], __float_as_uint(sqrtf(s)));
}

// ---------------- K23: fused ----------------
#define SQH   0
#define SQL   32768
#define SCKH  65536
#define SCKL  98304
#define SPS   131072
#define SOC   98304
#define SBUF  32768
#define BUFSZ 32768
#define VHIO  16384
#define SMTOT 163840

__global__ __launch_bounds__(256, 1) void k23_fused(
    const float* __restrict__ q, const float* __restrict__ w,
    float* __restrict__ out)
{
    extern __shared__ char smem[];
    uint32_t sb = smem_u32(smem);
    float* psum_sh = reinterpret_cast<float*>(smem + SPS);
    float* oc_sh = reinterpret_cast<float*>(smem + SOC);
    int tid = threadIdx.x;
    int wp = tid >> 5, lane = tid & 31;
    int ridx = (int)gridDim.x - 1 - (int)blockIdx.x;
    int tile = ridx >> 1;
    int kh = ridx & 1;
    int t0 = tile * TQ;
    int grp = lane >> 3;
    int jcl = (lane & 3) * 2;

    __shared__ int s_list[36];
    __shared__ int s_n;
    __shared__ unsigned s_union;

    int t_a = t0 + 2 * wp;
    int t_b = t_a + 1;
    int g = lane >> 2;
    int h = kh * GQ + g;

    if (tid == 0) s_union = 0u;

    // ---- stage QH/QL + CKH/CKL ----
    for (int i = tid; i < 128 * 16; i += 256) {
        int row = i >> 4, c16 = i & 15;
        uint32_t off = (uint32_t)row * 256u + (uint32_t)((c16 ^ (row & 7)) << 4);
        int qrow = (t0 + (row >> 3)) * H_HEADS + kh * GQ + (row & 7);
        CP_ASYNC16(sb + SQH + off, g_qh16 + (size_t)qrow * DDIM + c16 * 8);
        CP_ASYNC16(sb + SQL + off, g_ql16 + (size_t)qrow * DDIM + c16 * 8);
        CP_ASYNC16(sb + SCKH + off, &g_ckhi[kh][row][c16 * 8]);
        CP_ASYNC16(sb + SCKL + off, &g_cklo[kh][row][c16 * 8]);
    }
    CP_COMMIT();

    float kmaxv = __uint_as_float(g_kmax[kh]);
    float Ua, Ub;
    {
        const float4* q4 = reinterpret_cast<const float4*>(q);
        float s2 = 0.f;
        const float4* qr = q4 + ((size_t)(t_a * H_HEADS + h)) * 32;
#pragma unroll 8
        for (int d4 = 0; d4 < 32; d4++) { float4 a = qr[d4]; s2 += a.x*a.x + a.y*a.y + a.z*a.z + a.w*a.w; }
        Ua = SCALE_F * sqrtf(s2) * kmaxv - EXP_SHIFT;
        s2 = 0.f;
        qr = q4 + ((size_t)(t_b * H_HEADS + h)) * 32;
#pragma unroll 8
        for (int d4 = 0; d4 < 32; d4++) { float4 a = qr[d4]; s2 += a.x*a.x + a.y*a.y + a.z*a.z + a.w*a.w; }
        Ub = SCALE_F * sqrtf(s2) * kmaxv - EXP_SHIFT;
    }

    CP_WAIT0();
    __syncthreads();

    int nva = (t_a >= 31) ? ((t_a - 31) / 16 + 1) : 0;
    int nvb = (t_b >= 31) ? ((t_b - 31) / 16 + 1) : 0;

    // ---- Q-hi fragments (both phases) ----
    uint32_t ah[8][4];
    {
        int row = 16 * wp + (grp & 1) * 8 + (lane & 7);
        uint32_t rb = (uint32_t)row * 256u, rx = (uint32_t)(row & 7);
#pragma unroll
        for (int kt = 0; kt < 8; kt++) {
            uint32_t cq = (uint32_t)(kt * 2 + (grp >> 1));
            ldsm4(ah[kt], sb + SQH + rb + ((cq ^ rx) << 4));
        }
    }

    unsigned selm_a, selm_b;
    const __half* khbase = g_kh16 + (size_t)kh * T_LEN * DDIM;
    const __half* vhbase = g_vh16 + (size_t)kh * T_LEN * DDIM;

    // ================= PHASE 1 =================
    {
        float s[16][4];
#pragma unroll
        for (int i = 0; i < 16; i++)
#pragma unroll
            for (int c = 0; c < 4; c++) s[i][c] = 0.f;

#pragma unroll
        for (int np = 0; np < 8; np++) {
            if (np * 16 < nvb) {
                int keyq = np * 16 + (grp >> 1) * 8 + (lane & 7);
                uint32_t kb = (uint32_t)keyq * 256u, rxk = (uint32_t)(keyq & 7);
                int rowq = 16 * wp + (grp & 1) * 8 + (lane & 7);
                uint32_t rq = (uint32_t)rowq * 256u, rxq = (uint32_t)(rowq & 7);
#pragma unroll
                for (int kt = 0; kt < 8; kt++) {
                    uint32_t ck = (uint32_t)(kt * 2 + (grp & 1));
                    uint32_t bo = kb + ((ck ^ rxk) << 4);
                    uint32_t cq = (uint32_t)(kt * 2 + (grp >> 1));
                    uint32_t bh[4], bl[4], al[4];
                    ldsm4(bh, sb + SCKH + bo);
                    ldsm4(bl, sb + SCKL + bo);
                    ldsm4(al, sb + SQL + rq + ((cq ^ rxq) << 4));
                    mma16816h(s[2*np],   ah[kt], bh[0], bh[1]);
                    mma16816h(s[2*np+1], ah[kt], bh[2], bh[3]);
                    mma16816h(s[2*np],   ah[kt], bl[0], bl[1]);
                    mma16816h(s[2*np+1], ah[kt], bl[2], bl[3]);
                    mma16816h(s[2*np],   al,     bh[0], bh[1]);
                    mma16816h(s[2*np+1], al,     bh[2], bh[3]);
                }
            }
        }
        __syncthreads();

        for (int i = tid; i < 128 * 16; i += 256) {
            int row = i >> 4, c16 = i & 15;
            uint32_t off = (uint32_t)row * 256u + (uint32_t)((c16 ^ (row & 7)) << 4);
            CP_ASYNC16(sb + SCKH + off, &g_cvhi[kh][row][c16 * 8]);
        }
        for (int i = tid; i < 1024; i += 256) {
            int row = i >> 4, c16 = i & 15;
            size_t src = (size_t)row * DDIM + c16 * 8;
            uint32_t dst = sb + SBUF + ((uint32_t)row * 256u + (uint32_t)((c16 ^ (row & 7)) << 4));
            CP_ASYNC16(dst, khbase + src);
            CP_ASYNC16(dst + VHIO, vhbase + src);
        }
        CP_COMMIT();

        float ma = NEG_INF, mb = NEG_INF;
#pragma unroll
        for (int nt = 0; nt < 16; nt++) {
            if ((nt >> 1) * 16 < nvb) {
                int j0 = nt * 8 + jcl;
                if (j0 < nva)     ma = fmaxf(ma, s[nt][0] * SCALE_F);
                if (j0 + 1 < nva) ma = fmaxf(ma, s[nt][1] * SCALE_F);
                if (j0 < nvb)     mb = fmaxf(mb, s[nt][2] * SCALE_F);
                if (j0 + 1 < nvb) mb = fmaxf(mb, s[nt][3] * SCALE_F);
            }
        }
#pragma unroll
        for (int o = 1; o <= 2; o <<= 1) {
            ma = fmaxf(ma, __shfl_xor_sync(0xffffffffu, ma, o));
            mb = fmaxf(mb, __shfl_xor_sync(0xffffffffu, mb, o));
        }
        float la = 0.f, lb = 0.f;
#pragma unroll
        for (int nt = 0; nt < 16; nt++) {
            if ((nt >> 1) * 16 < nvb) {
                int j0 = nt * 8 + jcl;
                float e0 = (j0 < nva)     ? __expf(s[nt][0] * SCALE_F - ma) : 0.f;
                float e1 = (j0 + 1 < nva) ? __expf(s[nt][1] * SCALE_F - ma) : 0.f;
                float e2 = (j0 < nvb)     ? __expf(s[nt][2] * SCALE_F - mb) : 0.f;
                float e3 = (j0 + 1 < nvb) ? __expf(s[nt][3] * SCALE_F - mb) : 0.f;
                s[nt][0] = e0; s[nt][1] = e1; s[nt][2] = e2; s[nt][3] = e3;
                la += e0 + e1; lb += e2 + e3;
            }
        }
#pragma unroll
        for (int o = 1; o <= 2; o <<= 1) {
            la += __shfl_xor_sync(0xffffffffu, la, o);
            lb += __shfl_xor_sync(0xffffffffu, lb, o);
        }
        float inva = (nva > 0) ? 1.f / la : 0.f;
        float invb = (nvb > 0) ? 1.f / lb : 0.f;
#pragma unroll
        for (int nt = 0; nt < 16; nt++) {
            if ((nt >> 1) * 16 < nvb) {
                s[nt][0] *= inva; s[nt][1] *= inva;
                s[nt][2] *= invb; s[nt][3] *= invb;
            }
        }

#pragma unroll
        for (int nt = 0; nt < 16; nt++) {
            if ((nt >> 1) * 16 < nvb) {
                float a0 = s[nt][0], a1 = s[nt][1], b0 = s[nt][2], b1 = s[nt][3];
#pragma unroll
                for (int o = 4; o <= 16; o <<= 1) {
                    a0 += __shfl_xor_sync(0xffffffffu, a0, o);
                    a1 += __shfl_xor_sync(0xffffffffu, a1, o);
                    b0 += __shfl_xor_sync(0xffffffffu, b0, o);
                    b1 += __shfl_xor_sync(0xffffffffu, b1, o);
                }
                if (lane < 4) {
                    int j = nt * 8 + lane * 2;
                    psum_sh[(2 * wp) * 128 + j] = a0;
                    psum_sh[(2 * wp) * 128 + j + 1] = a1;
                    psum_sh[(2 * wp + 1) * 128 + j] = b0;
                    psum_sh[(2 * wp + 1) * 128 + j + 1] = b1;
                }
            }
        }
        __syncthreads();

        unsigned selres[2];
#pragma unroll
        for (int rep = 0; rep < 2; rep++) {
            int t = t0 + 2 * wp + rep;
            int qi = 2 * wp + rep;
            int nv = (t >= 31) ? ((t - 31) / 16 + 1) : 0;
            int b = lane;
            int tb = t >> 6;
            bool forced = (b < 1) || ((b <= tb) && (b >= tb - 1));
            bool valid = (b * 64 <= t);
            float sc;
            if (!valid) sc = -1e30f;
            else if (forced) sc = 1e30f;
            else {
                int jlo = 4 * b - 1; if (jlo < 0) jlo = 0;
                int jhi = 4 * b + 3; if (jhi > nv - 1) jhi = nv - 1;
                float ss = 0.f;
                for (int j = jlo; j <= jhi; j++) ss += psum_sh[qi * 128 + j];
                sc = ss;
            }
            unsigned u = __float_as_uint(sc);
            u = ((int)u < 0) ? ~u : (u | 0x80000000u);
            unsigned sel = 0u;
            for (int it = 0; it < 16; it++) {
                unsigned cur = ((sel >> b) & 1u) ? 0u : u;
                unsigned m = __reduce_max_sync(0xffffffffu, cur);
                unsigned ball = __ballot_sync(0xffffffffu, cur == m);
                sel |= (1u << (__ffs(ball) - 1));
            }
            selres[rep] = sel;
        }
        selm_a = selres[0];
        selm_b = selres[1];
        if (lane == 0) atomicOr(&s_union, selm_a | selm_b);

        uint32_t ph[8][4];
#pragma unroll
        for (int kp = 0; kp < 8; kp++) {
            if (kp * 16 < nvb) {
                ph[kp][0] = packh2(s[2*kp][0],   s[2*kp][1]);
                ph[kp][1] = packh2(s[2*kp][2],   s[2*kp][3]);
                ph[kp][2] = packh2(s[2*kp+1][0], s[2*kp+1][1]);
                ph[kp][3] = packh2(s[2*kp+1][2], s[2*kp+1][3]);
            }
        }

        CP_WAIT0();
        __syncthreads();

        float Oc[16][4];
#pragma unroll
        for (int i = 0; i < 16; i++)
#pragma unroll
            for (int c = 0; c < 4; c++) Oc[i][c] = 0.f;
#pragma unroll
        for (int kp = 0; kp < 8; kp++) {
            if (kp * 16 < nvb) {
                int keyv = kp * 16 + (grp & 1) * 8 + (lane & 7);
                uint32_t kb = (uint32_t)keyv * 256u, rxv = (uint32_t)(keyv & 7);
#pragma unroll
                for (int dp = 0; dp < 8; dp++) {
                    uint32_t c16 = (uint32_t)(dp * 2 + (grp >> 1));
                    uint32_t off = kb + ((c16 ^ rxv) << 4);
                    uint32_t vh[4];
                    ldsm4t(vh, sb + SCKH + off);
                    mma16816h(Oc[2*dp],   ph[kp], vh[0], vh[1]);
                    mma16816h(Oc[2*dp+1], ph[kp], vh[2], vh[3]);
                }
            }
        }
        __syncthreads();

#pragma unroll
        for (int nt = 0; nt < 16; nt++)
#pragma unroll
            for (int c = 0; c < 4; c++)
                oc_sh[(nt * 4 + c) * 256 + tid] = Oc[nt][c];
    }

    // ================= PHASE 2 =================
    __syncthreads();
    unsigned selu = s_union;
    int t_blk = t0 >> 6;

    if (tid == 0) {
        int n = 0;
        for (int b = 0; b <= t_blk; b++) {
            bool need = ((selu >> b) & 1u) || (b * 64 + 63 >= t0 - 511);
            if (need) s_list[n++] = b;
        }
        s_n = n;
    }
    __syncthreads();
    int nch = s_n;

    float Os[16][4], Ow[16][4];
#pragma unroll
    for (int i = 0; i < 16; i++)
#pragma unroll
        for (int c = 0; c < 4; c++) { Os[i][c] = 0.f; Ow[i][c] = 0.f; }
    float sum_sa = 0.f, sum_sb = 0.f, sum_wa = 0.f, sum_wb = 0.f;
    unsigned selw = selm_a | selm_b;
    int wlo = t_a - 511;

    for (int ci = 0; ci < nch; ci++) {
        int b = s_list[ci];
        uint32_t KB = sb + SBUF + (uint32_t)(ci & 1) * BUFSZ;

        if (ci > 0) {
            CP_WAIT0();
            __syncthreads();
        }
        if (ci + 1 < nch) {
            int bn = s_list[ci + 1];
            uint32_t NB = sb + SBUF + (uint32_t)((ci + 1) & 1) * BUFSZ;
            for (int i = tid; i < 1024; i += 256) {
                int row = i >> 4, c16 = i & 15;
                size_t src = (size_t)(bn * 64 + row) * DDIM + c16 * 8;
                uint32_t dst = NB + ((uint32_t)row * 256u + (uint32_t)((c16 ^ (row & 7)) << 4));
                CP_ASYNC16(dst, khbase + src);
                CP_ASYNC16(dst + VHIO, vhbase + src);
            }
            CP_COMMIT();
        }

        bool sel_w = (selw >> b) & 1u;
        bool win_w = (b * 64 + 63 >= wlo);
        if (!sel_w && !win_w) continue;
        bool sa = (selm_a >> b) & 1u, sb2 = (selm_b >> b) & 1u;
        bool limit_hi = (b == t_blk);
        bool limit_lo = win_w && !sel_w && (b * 64 < wlo);
        bool needs_wm = win_w && (b * 64 < t_b - 511);
        bool fast = !limit_hi && !needs_wm;

        // ---- pair-interleaved np body (proven schedule) + pair-level exact skips ----
#pragma unroll
        for (int npp = 0; npp < 2; npp++) {
            int npA = npp * 2;
            int baseA = b * 64 + npp * 32;
            if (limit_hi && baseA > t_b) continue;          // both slabs fully causal-masked
            if (limit_lo && baseA + 31 < wlo) continue;     // both slabs below window start

            float sA0[4] = {0.f,0.f,0.f,0.f}, sA1[4] = {0.f,0.f,0.f,0.f};
            float sB0[4] = {0.f,0.f,0.f,0.f}, sB1[4] = {0.f,0.f,0.f,0.f};
            {
                int keyqA = npA * 16 + (grp >> 1) * 8 + (lane & 7);
                int keyqB = keyqA + 16;
                uint32_t kbA = (uint32_t)keyqA * 256u, rxA = (uint32_t)(keyqA & 7);
                uint32_t kbB = (uint32_t)keyqB * 256u, rxB = (uint32_t)(keyqB & 7);
#pragma unroll
                for (int kt = 0; kt < 8; kt++) {
                    uint32_t ck = (uint32_t)(kt * 2 + (grp & 1));
                    uint32_t bhA[4], bhB[4];
                    ldsm4(bhA, KB + kbA + ((ck ^ rxA) << 4));
                    ldsm4(bhB, KB + kbB + ((ck ^ rxB) << 4));
                    mma16816h(sA0, ah[kt], bhA[0], bhA[1]);
                    mma16816h(sB0, ah[kt], bhB[0], bhB[1]);
                    mma16816h(sA1, ah[kt], bhA[2], bhA[3]);
                    mma16816h(sB1, ah[kt], bhB[2], bhB[3]);
                }
            }
            float eaA0 = __expf(sA0[0] * SCALE_F - Ua);
            float eaA1 = __expf(sA0[1] * SCALE_F - Ua);
            float ebA0 = __expf(sA0[2] * SCALE_F - Ub);
            float ebA1 = __expf(sA0[3] * SCALE_F - Ub);
            float faA0 = __expf(sA1[0] * SCALE_F - Ua);
            float faA1 = __expf(sA1[1] * SCALE_F - Ua);
            float fbA0 = __expf(sA1[2] * SCALE_F - Ub);
            float fbA1 = __expf(sA1[3] * SCALE_F - Ub);
            float eaB0 = __expf(sB0[0] * SCALE_F - Ua);
            float eaB1 = __expf(sB0[1] * SCALE_F - Ua);
            float ebB0 = __expf(sB0[2] * SCALE_F - Ub);
            float ebB1 = __expf(sB0[3] * SCALE_F - Ub);
            float faB0 = __expf(sB1[0] * SCALE_F - Ua);
            float faB1 = __expf(sB1[1] * SCALE_F - Ua);
            float fbB0 = __expf(sB1[2] * SCALE_F - Ub);
            float fbB1 = __expf(sB1[3] * SCALE_F - Ub);

            uint32_t psA[4], pwA[4], psB[4], pwB[4];
            if (fast) {
                if (sel_w) {
                    float v0 = sa ? eaA0 : 0.f, v1 = sa ? eaA1 : 0.f;
                    float v2 = sb2 ? ebA0 : 0.f, v3 = sb2 ? ebA1 : 0.f;
                    float v4 = sa ? faA0 : 0.f, v5 = sa ? faA1 : 0.f;
                    float v6 = sb2 ? fbA0 : 0.f, v7 = sb2 ? fbA1 : 0.f;
                    float u0 = sa ? eaB0 : 0.f, u1 = sa ? eaB1 : 0.f;
                    float u2 = sb2 ? ebB0 : 0.f, u3 = sb2 ? ebB1 : 0.f;
                    float u4 = sa ? faB0 : 0.f, u5 = sa ? faB1 : 0.f;
                    float u6 = sb2 ? fbB0 : 0.f, u7 = sb2 ? fbB1 : 0.f;
                    sum_sa += v0 + v1 + v4 + v5 + u0 + u1 + u4 + u5;
                    sum_sb += v2 + v3 + v6 + v7 + u2 + u3 + u6 + u7;
                    psA[0] = packh2(v0, v1); psA[1] = packh2(v2, v3);
                    psA[2] = packh2(v4, v5); psA[3] = packh2(v6, v7);
                    psB[0] = packh2(u0, u1); psB[1] = packh2(u2, u3);
                    psB[2] = packh2(u4, u5); psB[3] = packh2(u6, u7);
                }
                if (win_w) {
                    sum_wa += eaA0 + eaA1 + faA0 + faA1 + eaB0 + eaB1 + faB0 + faB1;
                    sum_wb += ebA0 + ebA1 + fbA0 + fbA1 + ebB0 + ebB1 + fbB0 + fbB1;
                    pwA[0] = packh2(eaA0, eaA1); pwA[1] = packh2(ebA0, ebA1);
                    pwA[2] = packh2(faA0, faA1); pwA[3] = packh2(fbA0, fbA1);
                    pwB[0] = packh2(eaB0, eaB1); pwB[1] = packh2(ebB0, ebB1);
                    pwB[2] = packh2(faB0, faB1); pwB[3] = packh2(fbB0, fbB1);
                }
            } else {
                int j0A = b * 64 + npA * 16 + jcl;
                int j0B = j0A + 16;
                if (sel_w) {
                    float v0 = (sa  && j0A     <= t_a) ? eaA0 : 0.f;
                    float v1 = (sa  && j0A + 1 <= t_a) ? eaA1 : 0.f;
                    float v2 = (sb2 && j0A     <= t_b) ? ebA0 : 0.f;
                    float v3 = (sb2 && j0A + 1 <= t_b) ? ebA1 : 0.f;
                    float v4 = (sa  && j0A + 8 <= t_a) ? faA0 : 0.f;
                    float v5 = (sa  && j0A + 9 <= t_a) ? faA1 : 0.f;
                    float v6 = (sb2 && j0A + 8 <= t_b) ? fbA0 : 0.f;
                    float v7 = (sb2 && j0A + 9 <= t_b) ? fbA1 : 0.f;
                    float u0 = (sa  && j0B     <= t_a) ? eaB0 : 0.f;
                    float u1 = (sa  && j0B + 1 <= t_a) ? eaB1 : 0.f;
                    float u2 = (sb2 && j0B     <= t_b) ? ebB0 : 0.f;
                    float u3 = (sb2 && j0B + 1 <= t_b) ? ebB1 : 0.f;
                    float u4 = (sa  && j0B + 8 <= t_a) ? faB0 : 0.f;
                    float u5 = (sa  && j0B + 9 <= t_a) ? faB1 : 0.f;
                    float u6 = (sb2 && j0B + 8 <= t_b) ? fbB0 : 0.f;
                    float u7 = (sb2 && j0B + 9 <= t_b) ? fbB1 : 0.f;
                    sum_sa += v0 + v1 + v4 + v5 + u0 + u1 + u4 + u5;
                    sum_sb += v2 + v3 + v6 + v7 + u2 + u3 + u6 + u7;
                    psA[0] = packh2(v0, v1); psA[1] = packh2(v2, v3);
                    psA[2] = packh2(v4, v5); psA[3] = packh2(v6, v7);
                    psB[0] = packh2(u0, u1); psB[1] = packh2(u2, u3);
                    psB[2] = packh2(u4, u5); psB[3] = packh2(u6, u7);
                }
                if (win_w) {
                    float v0 = (j0A     <= t_a && t_a - j0A < 512)       ? eaA0 : 0.f;
                    float v1 = (j0A + 1 <= t_a && t_a - (j0A + 1) < 512) ? eaA1 : 0.f;
                    float v2 = (j0A     <= t_b && t_b - j0A < 512)       ? ebA0 : 0.f;
                    float v3 = (j0A + 1 <= t_b && t_b - (j0A + 1) < 512) ? ebA1 : 0.f;
                    float v4 = (j0A + 8 <= t_a && t_a - (j0A + 8) < 512) ? faA0 : 0.f;
                    float v5 = (j0A + 9 <= t_a && t_a - (j0A + 9) < 512) ? faA1 : 0.f;
                    float v6 = (j0A + 8 <= t_b && t_b - (j0A + 8) < 512) ? fbA0 : 0.f;
                    float v7 = (j0A + 9 <= t_b && t_b - (j0A + 9) < 512) ? fbA1 : 0.f;
                    float u0 = (j0B     <= t_a && t_a - j0B < 512)       ? eaB0 : 0.f;
                    float u1 = (j0B + 1 <= t_a && t_a - (j0B + 1) < 512) ? eaB1 : 0.f;
                    float u2 = (j0B     <= t_b && t_b - j0B < 512)       ? ebB0 : 0.f;
                    float u3 = (j0B + 1 <= t_b && t_b - (j0B + 1) < 512) ? ebB1 : 0.f;
                    float u4 = (j0B + 8 <= t_a && t_a - (j0B + 8) < 512) ? faB0 : 0.f;
                    float u5 = (j0B + 9 <= t_a && t_a - (j0B + 9) < 512) ? faB1 : 0.f;
                    float u6 = (j0B + 8 <= t_b && t_b - (j0B + 8) < 512) ? fbB0 : 0.f;
                    float u7 = (j0B + 9 <= t_b && t_b - (j0B + 9) < 512) ? fbB1 : 0.f;
                    sum_wa += v0 + v1 + v4 + v5 + u0 + u1 + u4 + u5;
                    sum_wb += v2 + v3 + v6 + v7 + u2 + u3 + u6 + u7;
                    pwA[0] = packh2(v0, v1); pwA[1] = packh2(v2, v3);
                    pwA[2] = packh2(v4, v5); pwA[3] = packh2(v6, v7);
                    pwB[0] = packh2(u0, u1); pwB[1] = packh2(u2, u3);
                    pwB[2] = packh2(u4, u5); pwB[3] = packh2(u6, u7);
                }
            }

            {
                int keyvA = npA * 16 + (grp & 1) * 8 + (lane & 7);
                int keyvB = keyvA + 16;
                uint32_t kbA = (uint32_t)keyvA * 256u, rxA = (uint32_t)(keyvA & 7);
                uint32_t kbB = (uint32_t)keyvB * 256u, rxB = (uint32_t)(keyvB & 7);
#pragma unroll
                for (int dp = 0; dp < 8; dp++) {
                    uint32_t c16 = (uint32_t)(dp * 2 + (grp >> 1));
                    uint32_t vA[4], vB[4];
                    ldsm4t(vA, KB + VHIO + kbA + ((c16 ^ rxA) << 4));
                    ldsm4t(vB, KB + VHIO + kbB + ((c16 ^ rxB) << 4));
                    if (sel_w) {
                        mma16816h(Os[2 * dp],     psA, vA[0], vA[1]);
                        mma16816h(Os[2 * dp + 1], psA, vA[2], vA[3]);
                        mma16816h(Os[2 * dp],     psB, vB[0], vB[1]);
                        mma16816h(Os[2 * dp + 1], psB, vB[2], vB[3]);
                    }
                    if (win_w) {
                        mma16816h(Ow[2 * dp],     pwA, vA[0], vA[1]);
                        mma16816h(Ow[2 * dp + 1], pwA, vA[2], vA[3]);
                        mma16816h(Ow[2 * dp],     pwB, vB[0], vB[1]);
                        mma16816h(Ow[2 * dp + 1], pwB, vB[2], vB[3]);
                    }
                }
            }
        }
    }

    // ---- epilogue ----
#pragma unroll
    for (int o = 1; o <= 2; o <<= 1) {
        sum_sa += __shfl_xor_sync(0xffffffffu, sum_sa, o);
        sum_sb += __shfl_xor_sync(0xffffffffu, sum_sb, o);
        sum_wa += __shfl_xor_sync(0xffffffffu, sum_wa, o);
        sum_wb += __shfl_xor_sync(0xffffffffu, sum_wb, o);
    }
    float inv_sa = 1.f / sum_sa, inv_sb = 1.f / sum_sb;
    float inv_wa = 1.f / sum_wa, inv_wb = 1.f / sum_wb;

    const float* wa = w + ((size_t)(t_a * H_HEADS + h)) * 3;
    const float* wb = w + ((size_t)(t_b * H_HEADS + h)) * 3;
    float w0a = wa[0], w1a = wa[1], w2a = wa[2];
    float w0b = wb[0], w1b = wb[1], w2b = wb[2];

#pragma unroll
    for (int nt = 0; nt < 16; nt++) {
        int d0 = nt * 8 + jcl;
        float oca0 = oc_sh[(nt * 4 + 0) * 256 + tid];
        float oca1 = oc_sh[(nt * 4 + 1) * 256 + tid];
        float ocb0 = oc_sh[(nt * 4 + 2) * 256 + tid];
        float ocb1 = oc_sh[(nt * 4 + 3) * 256 + tid];
        float2 oa, ob;
        oa.x = w0a * oca0 + w1a * Os[nt][0] * inv_sa + w2a * Ow[nt][0] * inv_wa;
        oa.y = w0a * oca1 + w1a * Os[nt][1] * inv_sa + w2a * Ow[nt][1] * inv_wa;
        ob.x = w0b * ocb0 + w1b * Os[nt][2] * inv_sb + w2b * Ow[nt][2] * inv_wb;
        ob.y = w0b * ocb1 + w1b * Os[nt][3] * inv_sb + w2b * Ow[nt][3] * inv_wb;
        *reinterpret_cast<float2*>(out + ((size_t)(t_a * H_HEADS + h)) * DDIM + d0) = oa;
        *reinterpret_cast<float2*>(out + ((size_t)(t_b * H_HEADS + h)) * DDIM + d0) = ob;
    }
}

// ---------------- launch ----------------
extern "C" void kernel_launch(void* const* d_in, const int* in_sizes, int n_in,
                              void* d_out, int out_size) {
    const float* q = (const float*)d_in[0];
    const float* k = (const float*)d_in[1];
    const float* v = (const float*)d_in[2];
    const float* w = (const float*)d_in[3];
    float* out = (float*)d_out;

    cudaFuncSetAttribute(k23_fused, cudaFuncAttributeMaxDynamicSharedMemorySize, SMTOT);

    k0_split<<<1024, 256>>>(q, k, v);
    k1_compress<<<dim3(NCMP, KHN), DDIM>>>(k, v);
    k1b_knorm<<<dim3(T_LEN, KHN), 32>>>(k);
    k23_fused<<<dim3(T_LEN / TQ * KHN, 1), 256, SMTOT>>>(q, w, out);
}

// round 17
// speedup vs baseline: 1.0403x; 1.0058x over previous
#include <cuda_runtime.h>
#include <cuda_fp16.h>
#include <math.h>
#include <stdint.h>

#define T_LEN 2048
#define H_HEADS 16
#define KHN 2
#define GQ 8
#define DDIM 128
#define NCMP 127
#define TQ 16
#define SCALE_F 0.08838834765f
#define EXP_SHIFT 10.3972077f   /* ln(2^15) */
#define NEG_INF (-INFINITY)

// ---------------- scratch ----------------
__device__ unsigned g_kmax[KHN];

__device__ __align__(16) __half g_qh16[T_LEN * H_HEADS * DDIM];
__device__ __align__(16) __half g_ql16[T_LEN * H_HEADS * DDIM];
__device__ __align__(16) __half g_kh16[KHN * T_LEN * DDIM];
__device__ __align__(16) __half g_vh16[KHN * T_LEN * DDIM];
__device__ __align__(16) __half g_ckhi[KHN][128][DDIM];
__device__ __align__(16) __half g_cklo[KHN][128][DDIM];
__device__ __align__(16) __half g_cvhi[KHN][128][DDIM];

// ---------------- helpers ----------------
__device__ __forceinline__ uint32_t smem_u32(const void* p) {
    uint32_t a;
    asm("{ .reg .u64 t; cvta.to.shared.u64 t, %1; cvt.u32.u64 %0, t; }" : "=r"(a) : "l"(p));
    return a;
}
__device__ __forceinline__ void mma16816h(float* d, const uint32_t* a, uint32_t b0, uint32_t b1) {
    asm volatile("mma.sync.aligned.m16n8k16.row.col.f32.f16.f16.f32 "
        "{%0,%1,%2,%3},{%4,%5,%6,%7},{%8,%9},{%0,%1,%2,%3};"
        : "+f"(d[0]), "+f"(d[1]), "+f"(d[2]), "+f"(d[3])
        : "r"(a[0]), "r"(a[1]), "r"(a[2]), "r"(a[3]), "r"(b0), "r"(b1));
}
__device__ __forceinline__ void ldsm4(uint32_t* r, uint32_t addr) {
    asm volatile("ldmatrix.sync.aligned.m8n8.x4.shared.b16 {%0,%1,%2,%3}, [%4];"
        : "=r"(r[0]), "=r"(r[1]), "=r"(r[2]), "=r"(r[3]) : "r"(addr));
}
__device__ __forceinline__ void ldsm4t(uint32_t* r, uint32_t addr) {
    asm volatile("ldmatrix.sync.aligned.m8n8.x4.trans.shared.b16 {%0,%1,%2,%3}, [%4];"
        : "=r"(r[0]), "=r"(r[1]), "=r"(r[2]), "=r"(r[3]) : "r"(addr));
}
__device__ __forceinline__ uint32_t packh2(float a, float b) {
    __half2 h = __floats2half2_rn(a, b);
    return *reinterpret_cast<uint32_t*>(&h);
}
#define CP_ASYNC16(dst, src) \
    asm volatile("cp.async.cg.shared.global [%0], [%1], 16;" :: "r"(dst), "l"(src) : "memory")
#define CP_COMMIT() asm volatile("cp.async.commit_group;" ::: "memory")
#define CP_WAIT0()  asm volatile("cp.async.wait_group 0;" ::: "memory")

// ---------------- K0: fused pre-split (q 2-way, k/v fp16) + k-row norms ----------------
// blocks [0, 512): warp-per-row K/V convert + ||k|| (8 warps/block, 4096 rows)
// blocks [512, 768): grid-stride Q split
__global__ __launch_bounds__(256) void k0_prep(const float* __restrict__ q,
                                               const float* __restrict__ k,
                                               const float* __restrict__ v) {
    int bid = blockIdx.x;
    if (bid < 512) {
        int wp = threadIdx.x >> 5, lane = threadIdx.x & 31;
        int row = bid * 8 + wp;            // row = t*KHN + kh
        int t = row >> 1, kh = row & 1;
        const float4* kr = reinterpret_cast<const float4*>(k) + (size_t)row * 32;
        const float4* vr = reinterpret_cast<const float4*>(v) + (size_t)row * 32;
        float4 a = kr[lane];
        float4 b = vr[lane];
        // convert to fp16 (dest layout: [kh][t][d])
        size_t o = ((size_t)kh * T_LEN + t) * DDIM + lane * 4;
        __half2 k01 = __floats2half2_rn(a.x, a.y);
        __half2 k23 = __floats2half2_rn(a.z, a.w);
        __half2 v01 = __floats2half2_rn(b.x, b.y);
        __half2 v23 = __floats2half2_rn(b.z, b.w);
        *reinterpret_cast<__half2*>(g_kh16 + o)     = k01;
        *reinterpret_cast<__half2*>(g_kh16 + o + 2) = k23;
        *reinterpret_cast<__half2*>(g_vh16 + o)     = v01;
        *reinterpret_cast<__half2*>(g_vh16 + o + 2) = v23;
        // ||k||: identical reduction order to the old k1b (bit-exact g_kmax)
        float s = a.x * a.x + a.y * a.y + a.z * a.z + a.w * a.w;
        for (int off = 16; off; off >>= 1) s += __shfl_xor_sync(0xffffffffu, s, off);
        if (lane == 0) atomicMax(&g_kmax[kh], __float_as_uint(sqrtf(s)));
    } else {
        const int n_q = T_LEN * H_HEADS * DDIM;
        int stride = 256 * 256;
        int idx = (bid - 512) * 256 + threadIdx.x;
        for (int i = idx; i < n_q; i += stride) {
            float x = q[i];
            __half hh = __float2half_rn(x);
            g_qh16[i] = hh;
            g_ql16[i] = __float2half_rn(x - __half2float(hh));
        }
    }
}

// ---------------- K1: compressed K/V ----------------
__global__ void k1_compress(const float* __restrict__ k, const float* __restrict__ v) {
    int j = blockIdx.x, kh = blockIdx.y, d = threadIdx.x;
    int s = j * 16;
    float sk = 0.f, sv = 0.f;
#pragma unroll 8
    for (int i = 0; i < 32; i++) {
        sk += k[((size_t)(s + i) * KHN + kh) * DDIM + d];
        sv += v[((size_t)(s + i) * KHN + kh) * DDIM + d];
    }
    float ck = sk * (1.f / 32.f), cv = sv * (1.f / 32.f);
    __half h = __float2half_rn(ck);
    g_ckhi[kh][j][d] = h;
    g_cklo[kh][j][d] = __float2half_rn(ck - __half2float(h));
    g_cvhi[kh][j][d] = __float2half_rn(cv);
}

// ---------------- K23: fused ----------------
#define SQH   0
#define SQL   32768
#define SCKH  65536
#define SCKL  98304
#define SPS   131072
#define SOC   98304
#define SBUF  32768
#define BUFSZ 32768
#define VHIO  16384
#define SMTOT 163840

__global__ __launch_bounds__(256, 1) void k23_fused(
    const float* __restrict__ q, const float* __restrict__ w,
    float* __restrict__ out)
{
    extern __shared__ char smem[];
    uint32_t sb = smem_u32(smem);
    float* psum_sh = reinterpret_cast<float*>(smem + SPS);
    float* oc_sh = reinterpret_cast<float*>(smem + SOC);
    int tid = threadIdx.x;
    int wp = tid >> 5, lane = tid & 31;
    int ridx = (int)gridDim.x - 1 - (int)blockIdx.x;
    int tile = ridx >> 1;
    int kh = ridx & 1;
    int t0 = tile * TQ;
    int grp = lane >> 3;
    int jcl = (lane & 3) * 2;

    __shared__ int s_list[36];
    __shared__ int s_n;
    __shared__ unsigned s_union;

    int t_a = t0 + 2 * wp;
    int t_b = t_a + 1;
    int g = lane >> 2;
    int h = kh * GQ + g;

    if (tid == 0) s_union = 0u;

    // ---- stage QH/QL + CKH/CKL ----
    for (int i = tid; i < 128 * 16; i += 256) {
        int row = i >> 4, c16 = i & 15;
        uint32_t off = (uint32_t)row * 256u + (uint32_t)((c16 ^ (row & 7)) << 4);
        int qrow = (t0 + (row >> 3)) * H_HEADS + kh * GQ + (row & 7);
        CP_ASYNC16(sb + SQH + off, g_qh16 + (size_t)qrow * DDIM + c16 * 8);
        CP_ASYNC16(sb + SQL + off, g_ql16 + (size_t)qrow * DDIM + c16 * 8);
        CP_ASYNC16(sb + SCKH + off, &g_ckhi[kh][row][c16 * 8]);
        CP_ASYNC16(sb + SCKL + off, &g_cklo[kh][row][c16 * 8]);
    }
    CP_COMMIT();

    float kmaxv = __uint_as_float(g_kmax[kh]);
    float Ua, Ub;
    {
        const float4* q4 = reinterpret_cast<const float4*>(q);
        float s2 = 0.f;
        const float4* qr = q4 + ((size_t)(t_a * H_HEADS + h)) * 32;
#pragma unroll 8
        for (int d4 = 0; d4 < 32; d4++) { float4 a = qr[d4]; s2 += a.x*a.x + a.y*a.y + a.z*a.z + a.w*a.w; }
        Ua = SCALE_F * sqrtf(s2) * kmaxv - EXP_SHIFT;
        s2 = 0.f;
        qr = q4 + ((size_t)(t_b * H_HEADS + h)) * 32;
#pragma unroll 8
        for (int d4 = 0; d4 < 32; d4++) { float4 a = qr[d4]; s2 += a.x*a.x + a.y*a.y + a.z*a.z + a.w*a.w; }
        Ub = SCALE_F * sqrtf(s2) * kmaxv - EXP_SHIFT;
    }

    CP_WAIT0();
    __syncthreads();

    int nva = (t_a >= 31) ? ((t_a - 31) / 16 + 1) : 0;
    int nvb = (t_b >= 31) ? ((t_b - 31) / 16 + 1) : 0;

    uint32_t ah[8][4];
    {
        int row = 16 * wp + (grp & 1) * 8 + (lane & 7);
        uint32_t rb = (uint32_t)row * 256u, rx = (uint32_t)(row & 7);
#pragma unroll
        for (int kt = 0; kt < 8; kt++) {
            uint32_t cq = (uint32_t)(kt * 2 + (grp >> 1));
            ldsm4(ah[kt], sb + SQH + rb + ((cq ^ rx) << 4));
        }
    }

    unsigned selm_a, selm_b;
    const __half* khbase = g_kh16 + (size_t)kh * T_LEN * DDIM;
    const __half* vhbase = g_vh16 + (size_t)kh * T_LEN * DDIM;

    // ================= PHASE 1 =================
    {
        float s[16][4];
#pragma unroll
        for (int i = 0; i < 16; i++)
#pragma unroll
            for (int c = 0; c < 4; c++) s[i][c] = 0.f;

#pragma unroll
        for (int np = 0; np < 8; np++) {
            if (np * 16 < nvb) {
                int keyq = np * 16 + (grp >> 1) * 8 + (lane & 7);
                uint32_t kb = (uint32_t)keyq * 256u, rxk = (uint32_t)(keyq & 7);
                int rowq = 16 * wp + (grp & 1) * 8 + (lane & 7);
                uint32_t rq = (uint32_t)rowq * 256u, rxq = (uint32_t)(rowq & 7);
#pragma unroll
                for (int kt = 0; kt < 8; kt++) {
                    uint32_t ck = (uint32_t)(kt * 2 + (grp & 1));
                    uint32_t bo = kb + ((ck ^ rxk) << 4);
                    uint32_t cq = (uint32_t)(kt * 2 + (grp >> 1));
                    uint32_t bh[4], bl[4], al[4];
                    ldsm4(bh, sb + SCKH + bo);
                    ldsm4(bl, sb + SCKL + bo);
                    ldsm4(al, sb + SQL + rq + ((cq ^ rxq) << 4));
                    mma16816h(s[2*np],   ah[kt], bh[0], bh[1]);
                    mma16816h(s[2*np+1], ah[kt], bh[2], bh[3]);
                    mma16816h(s[2*np],   ah[kt], bl[0], bl[1]);
                    mma16816h(s[2*np+1], ah[kt], bl[2], bl[3]);
                    mma16816h(s[2*np],   al,     bh[0], bh[1]);
                    mma16816h(s[2*np+1], al,     bh[2], bh[3]);
                }
            }
        }
        __syncthreads();

        for (int i = tid; i < 128 * 16; i += 256) {
            int row = i >> 4, c16 = i & 15;
            uint32_t off = (uint32_t)row * 256u + (uint32_t)((c16 ^ (row & 7)) << 4);
            CP_ASYNC16(sb + SCKH + off, &g_cvhi[kh][row][c16 * 8]);
        }
        for (int i = tid; i < 1024; i += 256) {
            int row = i >> 4, c16 = i & 15;
            size_t src = (size_t)row * DDIM + c16 * 8;
            uint32_t dst = sb + SBUF + ((uint32_t)row * 256u + (uint32_t)((c16 ^ (row & 7)) << 4));
            CP_ASYNC16(dst, khbase + src);
            CP_ASYNC16(dst + VHIO, vhbase + src);
        }
        CP_COMMIT();

        float ma = NEG_INF, mb = NEG_INF;
#pragma unroll
        for (int nt = 0; nt < 16; nt++) {
            if ((nt >> 1) * 16 < nvb) {
                int j0 = nt * 8 + jcl;
                if (j0 < nva)     ma = fmaxf(ma, s[nt][0] * SCALE_F);
                if (j0 + 1 < nva) ma = fmaxf(ma, s[nt][1] * SCALE_F);
                if (j0 < nvb)     mb = fmaxf(mb, s[nt][2] * SCALE_F);
                if (j0 + 1 < nvb) mb = fmaxf(mb, s[nt][3] * SCALE_F);
            }
        }
#pragma unroll
        for (int o = 1; o <= 2; o <<= 1) {
            ma = fmaxf(ma, __shfl_xor_sync(0xffffffffu, ma, o));
            mb = fmaxf(mb, __shfl_xor_sync(0xffffffffu, mb, o));
        }
        float la = 0.f, lb = 0.f;
#pragma unroll
        for (int nt = 0; nt < 16; nt++) {
            if ((nt >> 1) * 16 < nvb) {
                int j0 = nt * 8 + jcl;
                float e0 = (j0 < nva)     ? __expf(s[nt][0] * SCALE_F - ma) : 0.f;
                float e1 = (j0 + 1 < nva) ? __expf(s[nt][1] * SCALE_F - ma) : 0.f;
                float e2 = (j0 < nvb)     ? __expf(s[nt][2] * SCALE_F - mb) : 0.f;
                float e3 = (j0 + 1 < nvb) ? __expf(s[nt][3] * SCALE_F - mb) : 0.f;
                s[nt][0] = e0; s[nt][1] = e1; s[nt][2] = e2; s[nt][3] = e3;
                la += e0 + e1; lb += e2 + e3;
            }
        }
#pragma unroll
        for (int o = 1; o <= 2; o <<= 1) {
            la += __shfl_xor_sync(0xffffffffu, la, o);
            lb += __shfl_xor_sync(0xffffffffu, lb, o);
        }
        float inva = (nva > 0) ? 1.f / la : 0.f;
        float invb = (nvb > 0) ? 1.f / lb : 0.f;
#pragma unroll
        for (int nt = 0; nt < 16; nt++) {
            if ((nt >> 1) * 16 < nvb) {
                s[nt][0] *= inva; s[nt][1] *= inva;
                s[nt][2] *= invb; s[nt][3] *= invb;
            }
        }

#pragma unroll
        for (int nt = 0; nt < 16; nt++) {
            if ((nt >> 1) * 16 < nvb) {
                float a0 = s[nt][0], a1 = s[nt][1], b0 = s[nt][2], b1 = s[nt][3];
#pragma unroll
                for (int o = 4; o <= 16; o <<= 1) {
                    a0 += __shfl_xor_sync(0xffffffffu, a0, o);
                    a1 += __shfl_xor_sync(0xffffffffu, a1, o);
                    b0 += __shfl_xor_sync(0xffffffffu, b0, o);
                    b1 += __shfl_xor_sync(0xffffffffu, b1, o);
                }
                if (lane < 4) {
                    int j = nt * 8 + lane * 2;
                    psum_sh[(2 * wp) * 128 + j] = a0;
                    psum_sh[(2 * wp) * 128 + j + 1] = a1;
                    psum_sh[(2 * wp + 1) * 128 + j] = b0;
                    psum_sh[(2 * wp + 1) * 128 + j + 1] = b1;
                }
            }
        }
        __syncthreads();

        unsigned selres[2];
#pragma unroll
        for (int rep = 0; rep < 2; rep++) {
            int t = t0 + 2 * wp + rep;
            int qi = 2 * wp + rep;
            int nv = (t >= 31) ? ((t - 31) / 16 + 1) : 0;
            int b = lane;
            int tb = t >> 6;
            bool forced = (b < 1) || ((b <= tb) && (b >= tb - 1));
            bool valid = (b * 64 <= t);
            float sc;
            if (!valid) sc = -1e30f;
            else if (forced) sc = 1e30f;
            else {
                int jlo = 4 * b - 1; if (jlo < 0) jlo = 0;
                int jhi = 4 * b + 3; if (jhi > nv - 1) jhi = nv - 1;
                float ss = 0.f;
                for (int j = jlo; j <= jhi; j++) ss += psum_sh[qi * 128 + j];
                sc = ss;
            }
            unsigned u = __float_as_uint(sc);
            u = ((int)u < 0) ? ~u : (u | 0x80000000u);
            unsigned sel = 0u;
            for (int it = 0; it < 16; it++) {
                unsigned cur = ((sel >> b) & 1u) ? 0u : u;
                unsigned m = __reduce_max_sync(0xffffffffu, cur);
                unsigned ball = __ballot_sync(0xffffffffu, cur == m);
                sel |= (1u << (__ffs(ball) - 1));
            }
            selres[rep] = sel;
        }
        selm_a = selres[0];
        selm_b = selres[1];
        if (lane == 0) atomicOr(&s_union, selm_a | selm_b);

        uint32_t ph[8][4];
#pragma unroll
        for (int kp = 0; kp < 8; kp++) {
            if (kp * 16 < nvb) {
                ph[kp][0] = packh2(s[2*kp][0],   s[2*kp][1]);
                ph[kp][1] = packh2(s[2*kp][2],   s[2*kp][3]);
                ph[kp][2] = packh2(s[2*kp+1][0], s[2*kp+1][1]);
                ph[kp][3] = packh2(s[2*kp+1][2], s[2*kp+1][3]);
            }
        }

        CP_WAIT0();
        __syncthreads();

        float Oc[16][4];
#pragma unroll
        for (int i = 0; i < 16; i++)
#pragma unroll
            for (int c = 0; c < 4; c++) Oc[i][c] = 0.f;
#pragma unroll
        for (int kp = 0; kp < 8; kp++) {
            if (kp * 16 < nvb) {
                int keyv = kp * 16 + (grp & 1) * 8 + (lane & 7);
                uint32_t kb = (uint32_t)keyv * 256u, rxv = (uint32_t)(keyv & 7);
#pragma unroll
                for (int dp = 0; dp < 8; dp++) {
                    uint32_t c16 = (uint32_t)(dp * 2 + (grp >> 1));
                    uint32_t off = kb + ((c16 ^ rxv) << 4);
                    uint32_t vh[4];
                    ldsm4t(vh, sb + SCKH + off);
                    mma16816h(Oc[2*dp],   ph[kp], vh[0], vh[1]);
                    mma16816h(Oc[2*dp+1], ph[kp], vh[2], vh[3]);
                }
            }
        }
        __syncthreads();

#pragma unroll
        for (int nt = 0; nt < 16; nt++)
#pragma unroll
            for (int c = 0; c < 4; c++)
                oc_sh[(nt * 4 + c) * 256 + tid] = Oc[nt][c];
    }

    // ================= PHASE 2 =================
    __syncthreads();
    unsigned selu = s_union;
    int t_blk = t0 >> 6;

    if (tid == 0) {
        int n = 0;
        for (int b = 0; b <= t_blk; b++) {
            bool need = ((selu >> b) & 1u) || (b * 64 + 63 >= t0 - 511);
            if (need) s_list[n++] = b;
        }
        s_n = n;
    }
    __syncthreads();
    int nch = s_n;

    float Os[16][4], Ow[16][4];
#pragma unroll
    for (int i = 0; i < 16; i++)
#pragma unroll
        for (int c = 0; c < 4; c++) { Os[i][c] = 0.f; Ow[i][c] = 0.f; }
    float sum_sa = 0.f, sum_sb = 0.f, sum_wa = 0.f, sum_wb = 0.f;
    unsigned selw = selm_a | selm_b;
    int wlo = t_a - 511;

    for (int ci = 0; ci < nch; ci++) {
        int b = s_list[ci];
        uint32_t KB = sb + SBUF + (uint32_t)(ci & 1) * BUFSZ;

        if (ci > 0) {
            CP_WAIT0();
            __syncthreads();
        }
        if (ci + 1 < nch) {
            int bn = s_list[ci + 1];
            uint32_t NB = sb + SBUF + (uint32_t)((ci + 1) & 1) * BUFSZ;
            for (int i = tid; i < 1024; i += 256) {
                int row = i >> 4, c16 = i & 15;
                size_t src = (size_t)(bn * 64 + row) * DDIM + c16 * 8;
                uint32_t dst = NB + ((uint32_t)row * 256u + (uint32_t)((c16 ^ (row & 7)) << 4));
                CP_ASYNC16(dst, khbase + src);
                CP_ASYNC16(dst + VHIO, vhbase + src);
            }
            CP_COMMIT();
        }

        bool sel_w = (selw >> b) & 1u;
        bool win_w = (b * 64 + 63 >= wlo);
        if (!sel_w && !win_w) continue;
        bool sa = (selm_a >> b) & 1u, sb2 = (selm_b >> b) & 1u;
        bool limit_hi = (b == t_blk);
        bool limit_lo = win_w && !sel_w && (b * 64 < wlo);
        bool needs_wm = win_w && (b * 64 < t_b - 511);
        bool fast = !limit_hi && !needs_wm;

#pragma unroll
        for (int npp = 0; npp < 2; npp++) {
            int npA = npp * 2;
            int baseA = b * 64 + npp * 32;
            if (limit_hi && baseA > t_b) continue;
            if (limit_lo && baseA + 31 < wlo) continue;

            float sA0[4] = {0.f,0.f,0.f,0.f}, sA1[4] = {0.f,0.f,0.f,0.f};
            float sB0[4] = {0.f,0.f,0.f,0.f}, sB1[4] = {0.f,0.f,0.f,0.f};
            {
                int keyqA = npA * 16 + (grp >> 1) * 8 + (lane & 7);
                int keyqB = keyqA + 16;
                uint32_t kbA = (uint32_t)keyqA * 256u, rxA = (uint32_t)(keyqA & 7);
                uint32_t kbB = (uint32_t)keyqB * 256u, rxB = (uint32_t)(keyqB & 7);
#pragma unroll
                for (int kt = 0; kt < 8; kt++) {
                    uint32_t ck = (uint32_t)(kt * 2 + (grp & 1));
                    uint32_t bhA[4], bhB[4];
                    ldsm4(bhA, KB + kbA + ((ck ^ rxA) << 4));
                    ldsm4(bhB, KB + kbB + ((ck ^ rxB) << 4));
                    mma16816h(sA0, ah[kt], bhA[0], bhA[1]);
                    mma16816h(sB0, ah[kt], bhB[0], bhB[1]);
                    mma16816h(sA1, ah[kt], bhA[2], bhA[3]);
                    mma16816h(sB1, ah[kt], bhB[2], bhB[3]);
                }
            }
            float eaA0 = __expf(sA0[0] * SCALE_F - Ua);
            float eaA1 = __expf(sA0[1] * SCALE_F - Ua);
            float ebA0 = __expf(sA0[2] * SCALE_F - Ub);
            float ebA1 = __expf(sA0[3] * SCALE_F - Ub);
            float faA0 = __expf(sA1[0] * SCALE_F - Ua);
            float faA1 = __expf(sA1[1] * SCALE_F - Ua);
            float fbA0 = __expf(sA1[2] * SCALE_F - Ub);
            float fbA1 = __expf(sA1[3] * SCALE_F - Ub);
            float eaB0 = __expf(sB0[0] * SCALE_F - Ua);
            float eaB1 = __expf(sB0[1] * SCALE_F - Ua);
            float ebB0 = __expf(sB0[2] * SCALE_F - Ub);
            float ebB1 = __expf(sB0[3] * SCALE_F - Ub);
            float faB0 = __expf(sB1[0] * SCALE_F - Ua);
            float faB1 = __expf(sB1[1] * SCALE_F - Ua);
            float fbB0 = __expf(sB1[2] * SCALE_F - Ub);
            float fbB1 = __expf(sB1[3] * SCALE_F - Ub);

            uint32_t psA[4], pwA[4], psB[4], pwB[4];
            if (fast) {
                if (sel_w) {
                    float v0 = sa ? eaA0 : 0.f, v1 = sa ? eaA1 : 0.f;
                    float v2 = sb2 ? ebA0 : 0.f, v3 = sb2 ? ebA1 : 0.f;
                    float v4 = sa ? faA0 : 0.f, v5 = sa ? faA1 : 0.f;
                    float v6 = sb2 ? fbA0 : 0.f, v7 = sb2 ? fbA1 : 0.f;
                    float u0 = sa ? eaB0 : 0.f, u1 = sa ? eaB1 : 0.f;
                    float u2 = sb2 ? ebB0 : 0.f, u3 = sb2 ? ebB1 : 0.f;
                    float u4 = sa ? faB0 : 0.f, u5 = sa ? faB1 : 0.f;
                    float u6 = sb2 ? fbB0 : 0.f, u7 = sb2 ? fbB1 : 0.f;
                    sum_sa += v0 + v1 + v4 + v5 + u0 + u1 + u4 + u5;
                    sum_sb += v2 + v3 + v6 + v7 + u2 + u3 + u6 + u7;
                    psA[0] = packh2(v0, v1); psA[1] = packh2(v2, v3);
                    psA[2] = packh2(v4, v5); psA[3] = packh2(v6, v7);
                    psB[0] = packh2(u0, u1); psB[1] = packh2(u2, u3);
                    psB[2] = packh2(u4, u5); psB[3] = packh2(u6, u7);
                }
                if (win_w) {
                    sum_wa += eaA0 + eaA1 + faA0 + faA1 + eaB0 + eaB1 + faB0 + faB1;
                    sum_wb += ebA0 + ebA1 + fbA0 + fbA1 + ebB0 + ebB1 + fbB0 + fbB1;
                    pwA[0] = packh2(eaA0, eaA1); pwA[1] = packh2(ebA0, ebA1);
                    pwA[2] = packh2(faA0, faA1); pwA[3] = packh2(fbA0, fbA1);
                    pwB[0] = packh2(eaB0, eaB1); pwB[1] = packh2(ebB0, ebB1);
                    pwB[2] = packh2(faB0, faB1); pwB[3] = packh2(fbB0, fbB1);
                }
            } else {
                int j0A = b * 64 + npA * 16 + jcl;
                int j0B = j0A + 16;
                if (sel_w) {
                    float v0 = (sa  && j0A     <= t_a) ? eaA0 : 0.f;
                    float v1 = (sa  && j0A + 1 <= t_a) ? eaA1 : 0.f;
                    float v2 = (sb2 && j0A     <= t_b) ? ebA0 : 0.f;
                    float v3 = (sb2 && j0A + 1 <= t_b) ? ebA1 : 0.f;
                    float v4 = (sa  && j0A + 8 <= t_a) ? faA0 : 0.f;
                    float v5 = (sa  && j0A + 9 <= t_a) ? faA1 : 0.f;
                    float v6 = (sb2 && j0A + 8 <= t_b) ? fbA0 : 0.f;
                    float v7 = (sb2 && j0A + 9 <= t_b) ? fbA1 : 0.f;
                    float u0 = (sa  && j0B     <= t_a) ? eaB0 : 0.f;
                    float u1 = (sa  && j0B + 1 <= t_a) ? eaB1 : 0.f;
                    float u2 = (sb2 && j0B     <= t_b) ? ebB0 : 0.f;
                    float u3 = (sb2 && j0B + 1 <= t_b) ? ebB1 : 0.f;
                    float u4 = (sa  && j0B + 8 <= t_a) ? faB0 : 0.f;
                    float u5 = (sa  && j0B + 9 <= t_a) ? faB1 : 0.f;
                    float u6 = (sb2 && j0B + 8 <= t_b) ? fbB0 : 0.f;
                    float u7 = (sb2 && j0B + 9 <= t_b) ? fbB1 : 0.f;
                    sum_sa += v0 + v1 + v4 + v5 + u0 + u1 + u4 + u5;
                    sum_sb += v2 + v3 + v6 + v7 + u2 + u3 + u6 + u7;
                    psA[0] = packh2(v0, v1); psA[1] = packh2(v2, v3);
                    psA[2] = packh2(v4, v5); psA[3] = packh2(v6, v7);
                    psB[0] = packh2(u0, u1); psB[1] = packh2(u2, u3);
                    psB[2] = packh2(u4, u5); psB[3] = packh2(u6, u7);
                }
                if (win_w) {
                    float v0 = (j0A     <= t_a && t_a - j0A < 512)       ? eaA0 : 0.f;
                    float v1 = (j0A + 1 <= t_a && t_a - (j0A + 1) < 512) ? eaA1 : 0.f;
                    float v2 = (j0A     <= t_b && t_b - j0A < 512)       ? ebA0 : 0.f;
                    float v3 = (j0A + 1 <= t_b && t_b - (j0A + 1) < 512) ? ebA1 : 0.f;
                    float v4 = (j0A + 8 <= t_a && t_a - (j0A + 8) < 512) ? faA0 : 0.f;
                    float v5 = (j0A + 9 <= t_a && t_a - (j0A + 9) < 512) ? faA1 : 0.f;
                    float v6 = (j0A + 8 <= t_b && t_b - (j0A + 8) < 512) ? fbA0 : 0.f;
                    float v7 = (j0A + 9 <= t_b && t_b - (j0A + 9) < 512) ? fbA1 : 0.f;
                    float u0 = (j0B     <= t_a && t_a - j0B < 512)       ? eaB0 : 0.f;
                    float u1 = (j0B + 1 <= t_a && t_a - (j0B + 1) < 512) ? eaB1 : 0.f;
                    float u2 = (j0B     <= t_b && t_b - j0B < 512)       ? ebB0 : 0.f;
                    float u3 = (j0B + 1 <= t_b && t_b - (j0B + 1) < 512) ? ebB1 : 0.f;
                    float u4 = (j0B + 8 <= t_a && t_a - (j0B + 8) < 512) ? faB0 : 0.f;
                    float u5 = (j0B + 9 <= t_a && t_a - (j0B + 9) < 512) ? faB1 : 0.f;
                    float u6 = (j0B + 8 <= t_b && t_b - (j0B + 8) < 512) ? fbB0 : 0.f;
                    float u7 = (j0B + 9 <= t_b && t_b - (j0B + 9) < 512) ? fbB1 : 0.f;
                    sum_wa += v0 + v1 + v4 + v5 + u0 + u1 + u4 + u5;
                    sum_wb += v2 + v3 + v6 + v7 + u2 + u3 + u6 + u7;
                    pwA[0] = packh2(v0, v1); pwA[1] = packh2(v2, v3);
                    pwA[2] = packh2(v4, v5); pwA[3] = packh2(v6, v7);
                    pwB[0] = packh2(u0, u1); pwB[1] = packh2(u2, u3);
                    pwB[2] = packh2(u4, u5); pwB[3] = packh2(u6, u7);
                }
            }

            {
                int keyvA = npA * 16 + (grp & 1) * 8 + (lane & 7);
                int keyvB = keyvA + 16;
                uint32_t kbA = (uint32_t)keyvA * 256u, rxA = (uint32_t)(keyvA & 7);
                uint32_t kbB = (uint32_t)keyvB * 256u, rxB = (uint32_t)(keyvB & 7);
#pragma unroll
                for (int dp = 0; dp < 8; dp++) {
                    uint32_t c16 = (uint32_t)(dp * 2 + (grp >> 1));
                    uint32_t vA[4], vB[4];
                    ldsm4t(vA, KB + VHIO + kbA + ((c16 ^ rxA) << 4));
                    ldsm4t(vB, KB + VHIO + kbB + ((c16 ^ rxB) << 4));
                    if (sel_w) {
                        mma16816h(Os[2 * dp],     psA, vA[0], vA[1]);
                        mma16816h(Os[2 * dp + 1], psA, vA[2], vA[3]);
                        mma16816h(Os[2 * dp],     psB, vB[0], vB[1]);
                        mma16816h(Os[2 * dp + 1], psB, vB[2], vB[3]);
                    }
                    if (win_w) {
                        mma16816h(Ow[2 * dp],     pwA, vA[0], vA[1]);
                        mma16816h(Ow[2 * dp + 1], pwA, vA[2], vA[3]);
                        mma16816h(Ow[2 * dp],     pwB, vB[0], vB[1]);
                        mma16816h(Ow[2 * dp + 1], pwB, vB[2], vB[3]);
                    }
                }
            }
        }
    }

    // ---- epilogue ----
#pragma unroll
    for (int o = 1; o <= 2; o <<= 1) {
        sum_sa += __shfl_xor_sync(0xffffffffu, sum_sa, o);
        sum_sb += __shfl_xor_sync(0xffffffffu, sum_sb, o);
        sum_wa += __shfl_xor_sync(0xffffffffu, sum_wa, o);
        sum_wb += __shfl_xor_sync(0xffffffffu, sum_wb, o);
    }
    float inv_sa = 1.f / sum_sa, inv_sb = 1.f / sum_sb;
    float inv_wa = 1.f / sum_wa, inv_wb = 1.f / sum_wb;

    const float* wa = w + ((size_t)(t_a * H_HEADS + h)) * 3;
    const float* wb = w + ((size_t)(t_b * H_HEADS + h)) * 3;
    float w0a = wa[0], w1a = wa[1], w2a = wa[2];
    float w0b = wb[0], w1b = wb[1], w2b = wb[2];

#pragma unroll
    for (int nt = 0; nt < 16; nt++) {
        int d0 = nt * 8 + jcl;
        float oca0 = oc_sh[(nt * 4 + 0) * 256 + tid];
        float oca1 = oc_sh[(nt * 4 + 1) * 256 + tid];
        float ocb0 = oc_sh[(nt * 4 + 2) * 256 + tid];
        float ocb1 = oc_sh[(nt * 4 + 3) * 256 + tid];
        float2 oa, ob;
        oa.x = w0a * oca0 + w1a * Os[nt][0] * inv_sa + w2a * Ow[nt][0] * inv_wa;
        oa.y = w0a * oca1 + w1a * Os[nt][1] * inv_sa + w2a * Ow[nt][1] * inv_wa;
        ob.x = w0b * ocb0 + w1b * Os[nt][2] * inv_sb + w2b * Ow[nt][2] * inv_wb;
        ob.y = w0b * ocb1 + w1b * Os[nt][3] * inv_sb + w2b * Ow[nt][3] * inv_wb;
        *reinterpret_cast<float2*>(out + ((size_t)(t_a * H_HEADS + h)) * DDIM + d0) = oa;
        *reinterpret_cast<float2*>(out + ((size_t)(t_b * H_HEADS + h)) * DDIM + d0) = ob;
    }
}

// ---------------- launch ----------------
extern "C" void kernel_launch(void* const* d_in, const int* in_sizes, int n_in,
                              void* d_out, int out_size) {
    const float* q = (const float*)d_in[0];
    const float* k = (const float*)d_in[1];
    const float* v = (const float*)d_in[2];
    const float* w = (const float*)d_in[3];
    float* out = (float*)d_out;

    cudaFuncSetAttribute(k23_fused, cudaFuncAttributeMaxDynamicSharedMemorySize, SMTOT);

    k0_prep<<<768, 256>>>(q, k, v);
    k1_compress<<<dim3(NCMP, KHN), DDIM>>>(k, v);
    k23_fused<<<dim3(T_LEN / TQ * KHN, 1), 256, SMTOT>>>(q, w, out);
}